// round 2
// baseline (speedup 1.0000x reference)
#include <cuda_runtime.h>
#include <cstdint>

#define NN 50000
#define DD 128
#define K2 256
#define EPS 1e-5f

// ---------------- scratch (device globals; no allocation allowed) ------------
__device__ float g_agg[NN * DD];   // per-layer aggregation buffer
__device__ float g_cnt[NN];        // in-degree counts
__device__ float g_inv[NN];        // 1/max(cnt,1)
__device__ float g_h0[NN * DD];    // layer 0 output
__device__ float g_h1[NN * DD];    // layer 1 output
__device__ float g_Wt[K2 * DD];    // combined transposed weights [k][j]
__device__ float g_stats[4 * DD];  // [sum | sumsq | scale | shift]

// ---------------- utility --------------------------------------------------
__global__ void zero_kernel(float* __restrict__ p, int n4) {
    int i = blockIdx.x * blockDim.x + threadIdx.x;
    if (i < n4) ((float4*)p)[i] = make_float4(0.f, 0.f, 0.f, 0.f);
}

// ---------------- degree counts (once per call) ------------------------------
__global__ void count_kernel(const int* __restrict__ ei, int E) {
    int e = blockIdx.x * blockDim.x + threadIdx.x;
    if (e < E) {
        int d = ei[E + e];
        if (d >= 0 && d < NN) atomicAdd(&g_cnt[d], 1.0f);
    }
}

__global__ void inv_kernel() {
    int n = blockIdx.x * blockDim.x + threadIdx.x;
    if (n < NN) g_inv[n] = 1.0f / fmaxf(g_cnt[n], 1.0f);
}

// ---------------- edge scatter: agg[dst] += x[src] ---------------------------
// one warp per edge; each lane handles 4 contiguous features via vector RED
__global__ void scatter_kernel(const float* __restrict__ x,
                               const int* __restrict__ ei, int E) {
    int gw = (blockIdx.x * blockDim.x + threadIdx.x) >> 5;
    int lane = threadIdx.x & 31;
    if (gw >= E) return;
    int s = 0, d = 0;
    if (lane == 0) { s = ei[gw]; d = ei[E + gw]; }
    s = __shfl_sync(0xffffffffu, s, 0);
    d = __shfl_sync(0xffffffffu, d, 0);
    float4 v = __ldg((const float4*)(x + (size_t)s * DD) + lane);
    float* dst = g_agg + (size_t)d * DD + lane * 4;
    asm volatile("red.global.add.v4.f32 [%0], {%1, %2, %3, %4};"
                 :: "l"(dst), "f"(v.x), "f"(v.y), "f"(v.z), "f"(v.w)
                 : "memory");
}

// ---------------- build combined transposed weight g_Wt[k][j] ---------------
__global__ void prep_w_kernel(const float* __restrict__ Wl,
                              const float* __restrict__ Wr) {
    int i = blockIdx.x * blockDim.x + threadIdx.x;
    if (i >= K2 * DD) return;
    int k = i >> 7, j = i & 127;
    g_Wt[i] = (k < DD) ? __ldg(&Wl[j * DD + k]) : __ldg(&Wr[j * DD + (k - DD)]);
}

// ---------------- fused dual GEMM: Y = [mean | x] @ Wt + bias ----------------
// block: 128 rows x 128 cols, 256 threads, 8x8 per thread, BK=16
__global__ __launch_bounds__(256, 2)
void gemm_kernel(const float* __restrict__ Xin,
                 const float* __restrict__ bias,
                 float* __restrict__ Y) {
    __shared__ float As[16][128];
    __shared__ float Bs[16][128];
    __shared__ float inv_s[128];

    int tid = threadIdx.x;
    int brow = blockIdx.x * 128;

    if (tid < 128) {
        int r = brow + tid;
        inv_s[tid] = (r < NN) ? g_inv[r] : 0.0f;
    }
    __syncthreads();

    float acc[8][8];
#pragma unroll
    for (int i = 0; i < 8; i++)
#pragma unroll
        for (int j = 0; j < 8; j++) acc[i][j] = 0.0f;

    int tr = tid >> 4, tc = tid & 15;

    for (int kc = 0; kc < K2; kc += 16) {
        const float* srcp;
        bool scaled;
        if (kc < DD) { srcp = g_agg + kc; scaled = true; }
        else         { srcp = Xin + (kc - DD); scaled = false; }

        // stage A tile: 128 rows x 16 k, transposed into As[k][m]
#pragma unroll
        for (int i = 0; i < 2; i++) {
            int l = tid + i * 256;          // 0..511
            int row = l >> 2, kq = l & 3;   // kq = float4 index within 16
            int r = brow + row;
            float4 v = make_float4(0.f, 0.f, 0.f, 0.f);
            if (r < NN) v = __ldg((const float4*)(srcp + (size_t)r * DD) + kq);
            if (scaled) {
                float sc = inv_s[row];
                v.x *= sc; v.y *= sc; v.z *= sc; v.w *= sc;
            }
            As[kq * 4 + 0][row] = v.x;
            As[kq * 4 + 1][row] = v.y;
            As[kq * 4 + 2][row] = v.z;
            As[kq * 4 + 3][row] = v.w;
        }
        // stage B tile: 16 k x 128 j (coalesced from pre-transposed g_Wt)
#pragma unroll
        for (int i = 0; i < 2; i++) {
            int l = tid + i * 256;          // 0..511 float4s
            int k = l >> 5, j4 = l & 31;
            float4 v = __ldg((const float4*)(g_Wt + (size_t)(kc + k) * DD) + j4);
            ((float4*)&Bs[k][0])[j4] = v;
        }
        __syncthreads();

#pragma unroll
        for (int k = 0; k < 16; k++) {
            float4 a0 = *(const float4*)&As[k][tr * 8];
            float4 a1 = *(const float4*)&As[k][tr * 8 + 4];
            float4 b0 = *(const float4*)&Bs[k][tc * 8];
            float4 b1 = *(const float4*)&Bs[k][tc * 8 + 4];
            float a[8] = {a0.x, a0.y, a0.z, a0.w, a1.x, a1.y, a1.z, a1.w};
            float b[8] = {b0.x, b0.y, b0.z, b0.w, b1.x, b1.y, b1.z, b1.w};
#pragma unroll
            for (int i = 0; i < 8; i++)
#pragma unroll
                for (int j = 0; j < 8; j++) acc[i][j] = fmaf(a[i], b[j], acc[i][j]);
        }
        __syncthreads();
    }

    // epilogue: add bias, store
#pragma unroll
    for (int i = 0; i < 8; i++) {
        int r = brow + tr * 8 + i;
        if (r >= NN) continue;
#pragma unroll
        for (int j = 0; j < 8; j += 4) {
            int c = tc * 8 + j;
            float4 o;
            o.x = acc[i][j + 0] + __ldg(&bias[c + 0]);
            o.y = acc[i][j + 1] + __ldg(&bias[c + 1]);
            o.z = acc[i][j + 2] + __ldg(&bias[c + 2]);
            o.w = acc[i][j + 3] + __ldg(&bias[c + 3]);
            *(float4*)(Y + (size_t)r * DD + c) = o;
        }
    }
}

// ---------------- BatchNorm stats ------------------------------------------
__global__ void stats_kernel(const float* __restrict__ Y) {
    int c = threadIdx.x;  // 128 threads = one per column
    float s = 0.f, sq = 0.f;
    for (int r = blockIdx.x; r < NN; r += gridDim.x) {
        float v = __ldg(&Y[(size_t)r * DD + c]);
        s += v;
        sq += v * v;
    }
    atomicAdd(&g_stats[c], s);
    atomicAdd(&g_stats[DD + c], sq);
}

__global__ void finalize_kernel(const float* __restrict__ gamma,
                                const float* __restrict__ beta) {
    int c = threadIdx.x;
    float m = g_stats[c] * (1.0f / NN);
    float var = g_stats[DD + c] * (1.0f / NN) - m * m;
    float sc = __ldg(&gamma[c]) * rsqrtf(var + EPS);
    g_stats[2 * DD + c] = sc;
    g_stats[3 * DD + c] = __ldg(&beta[c]) - m * sc;
}

__global__ void apply_kernel(float* __restrict__ Y, int relu) {
    int i = blockIdx.x * blockDim.x + threadIdx.x;
    if (i >= NN * (DD / 4)) return;
    float4 v = ((float4*)Y)[i];
    int c = (i & (DD / 4 - 1)) * 4;
    float s0 = g_stats[2 * DD + c + 0], b0 = g_stats[3 * DD + c + 0];
    float s1 = g_stats[2 * DD + c + 1], b1 = g_stats[3 * DD + c + 1];
    float s2 = g_stats[2 * DD + c + 2], b2 = g_stats[3 * DD + c + 2];
    float s3 = g_stats[2 * DD + c + 3], b3 = g_stats[3 * DD + c + 3];
    v.x = v.x * s0 + b0;
    v.y = v.y * s1 + b1;
    v.z = v.z * s2 + b2;
    v.w = v.w * s3 + b3;
    if (relu) {
        v.x = fmaxf(v.x, 0.f); v.y = fmaxf(v.y, 0.f);
        v.z = fmaxf(v.z, 0.f); v.w = fmaxf(v.w, 0.f);
    }
    ((float4*)Y)[i] = v;
}

// ---------------- launch ----------------------------------------------------
extern "C" void kernel_launch(void* const* d_in, const int* in_sizes, int n_in,
                              void* d_out, int out_size) {
    const float* x = (const float*)d_in[0];
    const int* ei = (const int*)d_in[1];   // JAX demotes int64 -> int32
    const float* Wl[3] = {(const float*)d_in[2], (const float*)d_in[7], (const float*)d_in[12]};
    const float* bl[3] = {(const float*)d_in[3], (const float*)d_in[8], (const float*)d_in[13]};
    const float* Wr[3] = {(const float*)d_in[4], (const float*)d_in[9], (const float*)d_in[14]};
    const float* gm[3] = {(const float*)d_in[5], (const float*)d_in[10], (const float*)d_in[15]};
    const float* bt[3] = {(const float*)d_in[6], (const float*)d_in[11], (const float*)d_in[16]};
    int E = in_sizes[1] / 2;

    void *p_agg, *p_cnt, *p_h0, *p_h1, *p_stats;
    cudaGetSymbolAddress(&p_agg, g_agg);
    cudaGetSymbolAddress(&p_cnt, g_cnt);
    cudaGetSymbolAddress(&p_h0, g_h0);
    cudaGetSymbolAddress(&p_h1, g_h1);
    cudaGetSymbolAddress(&p_stats, g_stats);

    // degree counts (NN = 50000 -> 12500 float4s exactly)
    zero_kernel<<<(12500 + 255) / 256, 256>>>((float*)p_cnt, 12500);
    count_kernel<<<(E + 255) / 256, 256>>>(ei, E);
    inv_kernel<<<(NN + 255) / 256, 256>>>();

    const int AGG4 = NN * DD / 4;  // 1.6M float4
    for (int L = 0; L < 3; L++) {
        const float* Xin = (L == 0) ? x : (L == 1 ? (const float*)p_h0 : (const float*)p_h1);
        float* Y = (L == 0) ? (float*)p_h0 : (L == 1 ? (float*)p_h1 : (float*)d_out);

        zero_kernel<<<(AGG4 + 255) / 256, 256>>>((float*)p_agg, AGG4);
        scatter_kernel<<<(E * 32 + 255) / 256, 256>>>(Xin, ei, E);
        prep_w_kernel<<<(K2 * DD + 255) / 256, 256>>>(Wl[L], Wr[L]);
        gemm_kernel<<<(NN + 127) / 128, 256>>>(Xin, bl[L], Y);

        zero_kernel<<<1, 64>>>((float*)p_stats, 64);  // zero sum+sumsq (256 floats)
        stats_kernel<<<512, 128>>>(Y);
        finalize_kernel<<<1, 128>>>(gm[L], bt[L]);
        apply_kernel<<<(NN * DD / 4 + 255) / 256, 256>>>(Y, L < 2 ? 1 : 0);
    }
}

// round 3
// speedup vs baseline: 1.2799x; 1.2799x over previous
#include <cuda_runtime.h>
#include <cstdint>

#define NN 50000
#define DD 128
#define K2 256
#define EE 800000
#define EPS 1e-5f

// ---------------- scratch (device globals) ----------------------------------
__device__ float g_agg[NN * DD];     // mean-aggregated features
__device__ float g_h0[NN * DD];      // layer 0 output
__device__ float g_h1[NN * DD];      // layer 1 output
__device__ float g_Wt[K2 * DD];      // combined transposed weights [k][j]
__device__ float g_stats[4 * DD];    // [sum | sumsq | scale | shift]
__device__ int   g_deg[NN];          // in-degree
__device__ int   g_rowptr[NN + 1];   // CSR row pointers
__device__ int   g_cursor[NN];       // fill cursors
__device__ int   g_col[EE];          // CSR column (source) indices

// ---------------- utility ---------------------------------------------------
__global__ void zero_f4(float* __restrict__ p, int n4) {
    int i = blockIdx.x * blockDim.x + threadIdx.x;
    if (i < n4) ((float4*)p)[i] = make_float4(0.f, 0.f, 0.f, 0.f);
}
__global__ void zero_i4(int* __restrict__ p, int n4) {
    int i = blockIdx.x * blockDim.x + threadIdx.x;
    if (i < n4) ((int4*)p)[i] = make_int4(0, 0, 0, 0);
}

// ---------------- CSR build (once per call) ----------------------------------
__global__ void count_kernel(const int* __restrict__ ei, int E) {
    int e = blockIdx.x * blockDim.x + threadIdx.x;
    if (e < E) {
        int d = ei[E + e];
        if (d >= 0 && d < NN) atomicAdd(&g_deg[d], 1);
    }
}

// single-block exclusive scan of g_deg -> g_rowptr / g_cursor
__global__ void scan_kernel() {
    __shared__ int sh[1024];
    __shared__ int carry_s;
    int tid = threadIdx.x;
    if (tid == 0) carry_s = 0;
    __syncthreads();
    for (int base = 0; base < NN; base += 1024) {
        int idx = base + tid;
        int v = (idx < NN) ? g_deg[idx] : 0;
        sh[tid] = v;
        __syncthreads();
#pragma unroll
        for (int off = 1; off < 1024; off <<= 1) {
            int t = (tid >= off) ? sh[tid - off] : 0;
            __syncthreads();
            sh[tid] += t;
            __syncthreads();
        }
        int incl = sh[tid];
        int tot = sh[1023];
        int carry = carry_s;
        if (idx < NN) {
            int excl = carry + incl - v;
            g_rowptr[idx] = excl;
            g_cursor[idx] = excl;
        }
        __syncthreads();
        if (tid == 0) carry_s = carry + tot;
        __syncthreads();
    }
    if (tid == 0) g_rowptr[NN] = carry_s;
}

__global__ void fill_kernel(const int* __restrict__ ei, int E) {
    int e = blockIdx.x * blockDim.x + threadIdx.x;
    if (e < E) {
        int s = ei[e];
        int d = ei[E + e];
        if (d >= 0 && d < NN) {
            int pos = atomicAdd(&g_cursor[d], 1);
            g_col[pos] = s;
        }
    }
}

// ---------------- mean gather: agg[n] = mean_{s in N(n)} x[s] ----------------
// one warp per node; lane handles 4 contiguous features
__global__ void gather_kernel(const float* __restrict__ x) {
    int w = (blockIdx.x * blockDim.x + threadIdx.x) >> 5;
    int lane = threadIdx.x & 31;
    if (w >= NN) return;
    int start = g_rowptr[w], end = g_rowptr[w + 1];
    float4 acc = make_float4(0.f, 0.f, 0.f, 0.f);
    int i = start;
    for (; i + 3 < end; i += 4) {
        int s0 = __ldg(&g_col[i + 0]);
        int s1 = __ldg(&g_col[i + 1]);
        int s2 = __ldg(&g_col[i + 2]);
        int s3 = __ldg(&g_col[i + 3]);
        float4 v0 = __ldg((const float4*)(x + (size_t)s0 * DD) + lane);
        float4 v1 = __ldg((const float4*)(x + (size_t)s1 * DD) + lane);
        float4 v2 = __ldg((const float4*)(x + (size_t)s2 * DD) + lane);
        float4 v3 = __ldg((const float4*)(x + (size_t)s3 * DD) + lane);
        acc.x += (v0.x + v1.x) + (v2.x + v3.x);
        acc.y += (v0.y + v1.y) + (v2.y + v3.y);
        acc.z += (v0.z + v1.z) + (v2.z + v3.z);
        acc.w += (v0.w + v1.w) + (v2.w + v3.w);
    }
    for (; i < end; i++) {
        int s = __ldg(&g_col[i]);
        float4 v = __ldg((const float4*)(x + (size_t)s * DD) + lane);
        acc.x += v.x; acc.y += v.y; acc.z += v.z; acc.w += v.w;
    }
    float sc = 1.0f / fmaxf((float)(end - start), 1.0f);
    acc.x *= sc; acc.y *= sc; acc.z *= sc; acc.w *= sc;
    ((float4*)(g_agg + (size_t)w * DD))[lane] = acc;
}

// ---------------- build combined transposed weight g_Wt[k][j] ---------------
__global__ void prep_w_kernel(const float* __restrict__ Wl,
                              const float* __restrict__ Wr) {
    int i = blockIdx.x * blockDim.x + threadIdx.x;
    if (i >= K2 * DD) return;
    int k = i >> 7, j = i & 127;
    g_Wt[i] = (k < DD) ? __ldg(&Wl[j * DD + k]) : __ldg(&Wr[j * DD + (k - DD)]);
}

// ---------------- fused dual GEMM: Y = [mean | x] @ Wt + bias ----------------
__global__ __launch_bounds__(256, 2)
void gemm_kernel(const float* __restrict__ Xin,
                 const float* __restrict__ bias,
                 float* __restrict__ Y) {
    __shared__ float As[16][128];
    __shared__ float Bs[16][128];

    int tid = threadIdx.x;
    int brow = blockIdx.x * 128;

    float acc[8][8];
#pragma unroll
    for (int i = 0; i < 8; i++)
#pragma unroll
        for (int j = 0; j < 8; j++) acc[i][j] = 0.0f;

    int tr = tid >> 4, tc = tid & 15;

    for (int kc = 0; kc < K2; kc += 16) {
        const float* srcp = (kc < DD) ? (g_agg + kc) : (Xin + (kc - DD));

#pragma unroll
        for (int i = 0; i < 2; i++) {
            int l = tid + i * 256;
            int row = l >> 2, kq = l & 3;
            int r = brow + row;
            float4 v = make_float4(0.f, 0.f, 0.f, 0.f);
            if (r < NN) v = __ldg((const float4*)(srcp + (size_t)r * DD) + kq);
            As[kq * 4 + 0][row] = v.x;
            As[kq * 4 + 1][row] = v.y;
            As[kq * 4 + 2][row] = v.z;
            As[kq * 4 + 3][row] = v.w;
        }
#pragma unroll
        for (int i = 0; i < 2; i++) {
            int l = tid + i * 256;
            int k = l >> 5, j4 = l & 31;
            float4 v = __ldg((const float4*)(g_Wt + (size_t)(kc + k) * DD) + j4);
            ((float4*)&Bs[k][0])[j4] = v;
        }
        __syncthreads();

#pragma unroll
        for (int k = 0; k < 16; k++) {
            float4 a0 = *(const float4*)&As[k][tr * 8];
            float4 a1 = *(const float4*)&As[k][tr * 8 + 4];
            float4 b0 = *(const float4*)&Bs[k][tc * 8];
            float4 b1 = *(const float4*)&Bs[k][tc * 8 + 4];
            float a[8] = {a0.x, a0.y, a0.z, a0.w, a1.x, a1.y, a1.z, a1.w};
            float b[8] = {b0.x, b0.y, b0.z, b0.w, b1.x, b1.y, b1.z, b1.w};
#pragma unroll
            for (int i = 0; i < 8; i++)
#pragma unroll
                for (int j = 0; j < 8; j++) acc[i][j] = fmaf(a[i], b[j], acc[i][j]);
        }
        __syncthreads();
    }

#pragma unroll
    for (int i = 0; i < 8; i++) {
        int r = brow + tr * 8 + i;
        if (r >= NN) continue;
#pragma unroll
        for (int j = 0; j < 8; j += 4) {
            int c = tc * 8 + j;
            float4 o;
            o.x = acc[i][j + 0] + __ldg(&bias[c + 0]);
            o.y = acc[i][j + 1] + __ldg(&bias[c + 1]);
            o.z = acc[i][j + 2] + __ldg(&bias[c + 2]);
            o.w = acc[i][j + 3] + __ldg(&bias[c + 3]);
            *(float4*)(Y + (size_t)r * DD + c) = o;
        }
    }
}

// ---------------- BatchNorm --------------------------------------------------
__global__ void stats_kernel(const float* __restrict__ Y) {
    int c = threadIdx.x;
    float s = 0.f, sq = 0.f;
    for (int r = blockIdx.x; r < NN; r += gridDim.x) {
        float v = __ldg(&Y[(size_t)r * DD + c]);
        s += v;
        sq += v * v;
    }
    atomicAdd(&g_stats[c], s);
    atomicAdd(&g_stats[DD + c], sq);
}

__global__ void finalize_kernel(const float* __restrict__ gamma,
                                const float* __restrict__ beta) {
    int c = threadIdx.x;
    float m = g_stats[c] * (1.0f / NN);
    float var = g_stats[DD + c] * (1.0f / NN) - m * m;
    float sc = __ldg(&gamma[c]) * rsqrtf(var + EPS);
    g_stats[2 * DD + c] = sc;
    g_stats[3 * DD + c] = __ldg(&beta[c]) - m * sc;
}

__global__ void apply_kernel(float* __restrict__ Y, int relu) {
    int i = blockIdx.x * blockDim.x + threadIdx.x;
    if (i >= NN * (DD / 4)) return;
    float4 v = ((float4*)Y)[i];
    int c = (i & (DD / 4 - 1)) * 4;
    float s0 = g_stats[2 * DD + c + 0], b0 = g_stats[3 * DD + c + 0];
    float s1 = g_stats[2 * DD + c + 1], b1 = g_stats[3 * DD + c + 1];
    float s2 = g_stats[2 * DD + c + 2], b2 = g_stats[3 * DD + c + 2];
    float s3 = g_stats[2 * DD + c + 3], b3 = g_stats[3 * DD + c + 3];
    v.x = v.x * s0 + b0;
    v.y = v.y * s1 + b1;
    v.z = v.z * s2 + b2;
    v.w = v.w * s3 + b3;
    if (relu) {
        v.x = fmaxf(v.x, 0.f); v.y = fmaxf(v.y, 0.f);
        v.z = fmaxf(v.z, 0.f); v.w = fmaxf(v.w, 0.f);
    }
    ((float4*)Y)[i] = v;
}

// ---------------- launch ----------------------------------------------------
extern "C" void kernel_launch(void* const* d_in, const int* in_sizes, int n_in,
                              void* d_out, int out_size) {
    const float* x = (const float*)d_in[0];
    const int* ei = (const int*)d_in[1];   // int32 on device (JAX x64 disabled)
    const float* Wl[3] = {(const float*)d_in[2], (const float*)d_in[7], (const float*)d_in[12]};
    const float* bl[3] = {(const float*)d_in[3], (const float*)d_in[8], (const float*)d_in[13]};
    const float* Wr[3] = {(const float*)d_in[4], (const float*)d_in[9], (const float*)d_in[14]};
    const float* gm[3] = {(const float*)d_in[5], (const float*)d_in[10], (const float*)d_in[15]};
    const float* bt[3] = {(const float*)d_in[6], (const float*)d_in[11], (const float*)d_in[16]};
    int E = in_sizes[1] / 2;

    void *p_h0, *p_h1, *p_stats, *p_deg;
    cudaGetSymbolAddress(&p_h0, g_h0);
    cudaGetSymbolAddress(&p_h1, g_h1);
    cudaGetSymbolAddress(&p_stats, g_stats);
    cudaGetSymbolAddress(&p_deg, g_deg);

    // ---- build CSR once per call ----
    zero_i4<<<(12500 + 255) / 256, 256>>>((int*)p_deg, 12500);  // NN/4 = 12500
    count_kernel<<<(E + 255) / 256, 256>>>(ei, E);
    scan_kernel<<<1, 1024>>>();
    fill_kernel<<<(E + 255) / 256, 256>>>(ei, E);

    for (int L = 0; L < 3; L++) {
        const float* Xin = (L == 0) ? x : (L == 1 ? (const float*)p_h0 : (const float*)p_h1);
        float* Y = (L == 0) ? (float*)p_h0 : (L == 1 ? (float*)p_h1 : (float*)d_out);

        gather_kernel<<<(NN * 32 + 255) / 256, 256>>>(Xin);
        prep_w_kernel<<<(K2 * DD + 255) / 256, 256>>>(Wl[L], Wr[L]);
        gemm_kernel<<<(NN + 127) / 128, 256>>>(Xin, bl[L], Y);

        zero_f4<<<1, 64>>>((float*)p_stats, 64);  // zero sum+sumsq
        stats_kernel<<<512, 128>>>(Y);
        finalize_kernel<<<1, 128>>>(gm[L], bt[L]);
        apply_kernel<<<(NN * DD / 4 + 255) / 256, 256>>>(Y, L < 2 ? 1 : 0);
    }
}

// round 4
// speedup vs baseline: 1.6172x; 1.2635x over previous
#include <cuda_runtime.h>
#include <cstdint>

#define NN 50000
#define DD 128
#define K2 256
#define EE 800000
#define EPS 1e-5f

// ---------------- scratch (device globals) ----------------------------------
__device__ float g_agg[NN * DD];     // mean-aggregated features
__device__ float g_h0[NN * DD];      // layer 0 output
__device__ float g_h1[NN * DD];      // layer 1 output
__device__ float g_Wt[K2 * DD];      // combined transposed weights [k][j]
__device__ float g_stats[4 * DD];    // [sum | sumsq | scale | shift]
__device__ int   g_deg[NN];          // in-degree
__device__ int   g_rowptr[NN + 1];   // CSR row pointers
__device__ int   g_cursor[NN];       // fill cursors
__device__ int   g_col[EE];          // CSR column (source) indices
__device__ int   g_bsum[64];         // scan block sums
__device__ int   g_boff[64];         // scan block offsets

// ---------------- utility ---------------------------------------------------
__global__ void zero_f4(float* __restrict__ p, int n4) {
    int i = blockIdx.x * blockDim.x + threadIdx.x;
    if (i < n4) ((float4*)p)[i] = make_float4(0.f, 0.f, 0.f, 0.f);
}
__global__ void zero_i4(int* __restrict__ p, int n4) {
    int i = blockIdx.x * blockDim.x + threadIdx.x;
    if (i < n4) ((int4*)p)[i] = make_int4(0, 0, 0, 0);
}

// ---------------- CSR build --------------------------------------------------
__global__ void count_kernel(const int* __restrict__ ei, int E) {
    int e = blockIdx.x * blockDim.x + threadIdx.x;
    if (e < E) {
        int d = ei[E + e];
        if (d >= 0 && d < NN) atomicAdd(&g_deg[d], 1);
    }
}

// block-level scan: writes per-element EXCLUSIVE (within block) to g_rowptr,
// block totals to g_bsum
__global__ void scan1_kernel() {
    __shared__ int wsum[32];
    int t = threadIdx.x, b = blockIdx.x;
    int idx = b * 1024 + t;
    int wid = t >> 5, lane = t & 31;
    int v = (idx < NN) ? g_deg[idx] : 0;
    // warp inclusive scan
    int incl = v;
#pragma unroll
    for (int off = 1; off < 32; off <<= 1) {
        int y = __shfl_up_sync(0xffffffffu, incl, off);
        if (lane >= off) incl += y;
    }
    if (lane == 31) wsum[wid] = incl;
    __syncthreads();
    if (wid == 0) {
        int s = wsum[lane];
        int si = s;
#pragma unroll
        for (int off = 1; off < 32; off <<= 1) {
            int y = __shfl_up_sync(0xffffffffu, si, off);
            if (lane >= off) si += y;
        }
        wsum[lane] = si;
    }
    __syncthreads();
    int woff = (wid > 0) ? wsum[wid - 1] : 0;
    if (idx < NN) g_rowptr[idx] = woff + incl - v;
    if (t == 0) g_bsum[b] = wsum[31];
}

// exclusive scan of block sums (<=64 entries)
__global__ void scan2_kernel(int nb) {
    __shared__ int sh[64];
    int t = threadIdx.x;
    sh[t] = (t < nb) ? g_bsum[t] : 0;
    __syncthreads();
#pragma unroll
    for (int off = 1; off < 64; off <<= 1) {
        int y = (t >= off) ? sh[t - off] : 0;
        __syncthreads();
        sh[t] += y;
        __syncthreads();
    }
    if (t < nb) g_boff[t] = sh[t] - g_bsum[t];
    if (t == 0) g_rowptr[NN] = sh[63];
}

__global__ void scan3_kernel() {
    int idx = blockIdx.x * 1024 + threadIdx.x;
    if (idx < NN) {
        int r = g_rowptr[idx] + g_boff[blockIdx.x];
        g_rowptr[idx] = r;
        g_cursor[idx] = r;
    }
}

__global__ void fill_kernel(const int* __restrict__ ei, int E) {
    int e = blockIdx.x * blockDim.x + threadIdx.x;
    if (e < E) {
        int s = ei[e];
        int d = ei[E + e];
        if (d >= 0 && d < NN) {
            int pos = atomicAdd(&g_cursor[d], 1);
            g_col[pos] = s;
        }
    }
}

// ---------------- mean gather: agg[n] = mean_{s in N(n)} x[s] ----------------
__global__ void gather_kernel(const float* __restrict__ x) {
    int w = (blockIdx.x * blockDim.x + threadIdx.x) >> 5;
    int lane = threadIdx.x & 31;
    if (w >= NN) return;
    int start = g_rowptr[w], end = g_rowptr[w + 1];
    float4 acc = make_float4(0.f, 0.f, 0.f, 0.f);
    int i = start;
    for (; i + 3 < end; i += 4) {
        int s0 = __ldg(&g_col[i + 0]);
        int s1 = __ldg(&g_col[i + 1]);
        int s2 = __ldg(&g_col[i + 2]);
        int s3 = __ldg(&g_col[i + 3]);
        float4 v0 = __ldg((const float4*)(x + (size_t)s0 * DD) + lane);
        float4 v1 = __ldg((const float4*)(x + (size_t)s1 * DD) + lane);
        float4 v2 = __ldg((const float4*)(x + (size_t)s2 * DD) + lane);
        float4 v3 = __ldg((const float4*)(x + (size_t)s3 * DD) + lane);
        acc.x += (v0.x + v1.x) + (v2.x + v3.x);
        acc.y += (v0.y + v1.y) + (v2.y + v3.y);
        acc.z += (v0.z + v1.z) + (v2.z + v3.z);
        acc.w += (v0.w + v1.w) + (v2.w + v3.w);
    }
    for (; i < end; i++) {
        int s = __ldg(&g_col[i]);
        float4 v = __ldg((const float4*)(x + (size_t)s * DD) + lane);
        acc.x += v.x; acc.y += v.y; acc.z += v.z; acc.w += v.w;
    }
    float sc = 1.0f / fmaxf((float)(end - start), 1.0f);
    acc.x *= sc; acc.y *= sc; acc.z *= sc; acc.w *= sc;
    ((float4*)(g_agg + (size_t)w * DD))[lane] = acc;
}

// ---------------- build combined transposed weight g_Wt[k][j] ---------------
__global__ void prep_w_kernel(const float* __restrict__ Wl,
                              const float* __restrict__ Wr) {
    int i = blockIdx.x * blockDim.x + threadIdx.x;
    if (i >= K2 * DD) return;
    int k = i >> 7, j = i & 127;
    g_Wt[i] = (k < DD) ? __ldg(&Wl[j * DD + k]) : __ldg(&Wr[j * DD + (k - DD)]);
}

// ---------------- 3xTF32 tensor-core GEMM -----------------------------------
// Y[128 x 128 tile] = [mean | x] @ Wt + bias  (K = 256)
// block = 128 threads = 4 warps (2x2), warp tile 64x64, BK = 16
#define ASTRIDE 20
#define BSTRIDE 136

__device__ __forceinline__ void split_tf32(float v, uint32_t& hi, uint32_t& lo) {
    asm("cvt.rna.tf32.f32 %0, %1;" : "=r"(hi) : "f"(v));
    float l = v - __uint_as_float(hi);
    asm("cvt.rna.tf32.f32 %0, %1;" : "=r"(lo) : "f"(l));
}

__device__ __forceinline__ void mma_tf32(float* d, uint32_t a0, uint32_t a1,
                                         uint32_t a2, uint32_t a3,
                                         uint32_t b0, uint32_t b1) {
    asm volatile(
        "mma.sync.aligned.m16n8k8.row.col.f32.tf32.tf32.f32 "
        "{%0,%1,%2,%3},{%4,%5,%6,%7},{%8,%9},{%0,%1,%2,%3};"
        : "+f"(d[0]), "+f"(d[1]), "+f"(d[2]), "+f"(d[3])
        : "r"(a0), "r"(a1), "r"(a2), "r"(a3), "r"(b0), "r"(b1));
}

__global__ __launch_bounds__(128, 2)
void gemm_kernel(const float* __restrict__ Xin,
                 const float* __restrict__ bias,
                 float* __restrict__ Y) {
    __shared__ float As_hi[128 * ASTRIDE];
    __shared__ float As_lo[128 * ASTRIDE];
    __shared__ float Bs_hi[16 * BSTRIDE];
    __shared__ float Bs_lo[16 * BSTRIDE];
    __shared__ float bias_s[128];

    int tid = threadIdx.x;
    int brow = blockIdx.x * 128;
    int wid = tid >> 5, lane = tid & 31;
    int group = lane >> 2, tg = lane & 3;
    int warp_m = (wid >> 1) * 64, warp_n = (wid & 1) * 64;

    if (tid < 128) bias_s[tid] = __ldg(&bias[tid]);

    float acc[4][8][4];
#pragma unroll
    for (int mt = 0; mt < 4; mt++)
#pragma unroll
        for (int nt = 0; nt < 8; nt++)
#pragma unroll
            for (int c = 0; c < 4; c++) acc[mt][nt][c] = 0.f;

    // register prefetch buffers
    float4 pa[4], pb[4];

    auto load_tiles = [&](int kc) {
        const float* srcp = (kc < DD) ? (g_agg + kc) : (Xin + (kc - DD));
#pragma unroll
        for (int i = 0; i < 4; i++) {
            int l = tid + i * 128;       // 0..511
            int row = l >> 2, kq = l & 3;
            int r = brow + row;
            pa[i] = (r < NN) ? __ldg((const float4*)(srcp + (size_t)r * DD) + kq)
                             : make_float4(0.f, 0.f, 0.f, 0.f);
        }
#pragma unroll
        for (int i = 0; i < 4; i++) {
            int l = tid + i * 128;       // 0..511
            int k = l >> 5, j4 = l & 31;
            pb[i] = __ldg((const float4*)(g_Wt + (size_t)(kc + k) * DD) + j4);
        }
    };

    auto store_tiles = [&]() {
#pragma unroll
        for (int i = 0; i < 4; i++) {
            int l = tid + i * 128;
            int row = l >> 2, kq = l & 3;
            float vv[4] = {pa[i].x, pa[i].y, pa[i].z, pa[i].w};
#pragma unroll
            for (int c = 0; c < 4; c++) {
                uint32_t h, lo;
                split_tf32(vv[c], h, lo);
                As_hi[row * ASTRIDE + kq * 4 + c] = __uint_as_float(h);
                As_lo[row * ASTRIDE + kq * 4 + c] = __uint_as_float(lo);
            }
        }
#pragma unroll
        for (int i = 0; i < 4; i++) {
            int l = tid + i * 128;
            int k = l >> 5, j4 = l & 31;
            float vv[4] = {pb[i].x, pb[i].y, pb[i].z, pb[i].w};
#pragma unroll
            for (int c = 0; c < 4; c++) {
                uint32_t h, lo;
                split_tf32(vv[c], h, lo);
                Bs_hi[k * BSTRIDE + j4 * 4 + c] = __uint_as_float(h);
                Bs_lo[k * BSTRIDE + j4 * 4 + c] = __uint_as_float(lo);
            }
        }
    };

    load_tiles(0);

    for (int kc = 0; kc < K2; kc += 16) {
        store_tiles();
        __syncthreads();
        if (kc + 16 < K2) load_tiles(kc + 16);

#pragma unroll
        for (int k0 = 0; k0 < 16; k0 += 8) {
            // B fragments for all 8 n-tiles
            uint32_t bh0[8], bh1[8], bl0[8], bl1[8];
#pragma unroll
            for (int nt = 0; nt < 8; nt++) {
                int n = warp_n + nt * 8 + group;
                bh0[nt] = __float_as_uint(Bs_hi[(k0 + tg) * BSTRIDE + n]);
                bh1[nt] = __float_as_uint(Bs_hi[(k0 + tg + 4) * BSTRIDE + n]);
                bl0[nt] = __float_as_uint(Bs_lo[(k0 + tg) * BSTRIDE + n]);
                bl1[nt] = __float_as_uint(Bs_lo[(k0 + tg + 4) * BSTRIDE + n]);
            }
#pragma unroll
            for (int mt = 0; mt < 4; mt++) {
                int m = warp_m + mt * 16;
                uint32_t ah0 = __float_as_uint(As_hi[(m + group) * ASTRIDE + k0 + tg]);
                uint32_t ah1 = __float_as_uint(As_hi[(m + group + 8) * ASTRIDE + k0 + tg]);
                uint32_t ah2 = __float_as_uint(As_hi[(m + group) * ASTRIDE + k0 + tg + 4]);
                uint32_t ah3 = __float_as_uint(As_hi[(m + group + 8) * ASTRIDE + k0 + tg + 4]);
                uint32_t al0 = __float_as_uint(As_lo[(m + group) * ASTRIDE + k0 + tg]);
                uint32_t al1 = __float_as_uint(As_lo[(m + group + 8) * ASTRIDE + k0 + tg]);
                uint32_t al2 = __float_as_uint(As_lo[(m + group) * ASTRIDE + k0 + tg + 4]);
                uint32_t al3 = __float_as_uint(As_lo[(m + group + 8) * ASTRIDE + k0 + tg + 4]);
#pragma unroll
                for (int nt = 0; nt < 8; nt++) {
                    mma_tf32(acc[mt][nt], ah0, ah1, ah2, ah3, bh0[nt], bh1[nt]);
                    mma_tf32(acc[mt][nt], al0, al1, al2, al3, bh0[nt], bh1[nt]);
                    mma_tf32(acc[mt][nt], ah0, ah1, ah2, ah3, bl0[nt], bl1[nt]);
                }
            }
        }
        __syncthreads();
    }

    // epilogue: bias + store
#pragma unroll
    for (int mt = 0; mt < 4; mt++) {
        int r0 = brow + warp_m + mt * 16 + group;
        int r1 = r0 + 8;
#pragma unroll
        for (int nt = 0; nt < 8; nt++) {
            int c = warp_n + nt * 8 + 2 * tg;
            float b0 = bias_s[c], b1 = bias_s[c + 1];
            if (r0 < NN) {
                float2 o = make_float2(acc[mt][nt][0] + b0, acc[mt][nt][1] + b1);
                *(float2*)(Y + (size_t)r0 * DD + c) = o;
            }
            if (r1 < NN) {
                float2 o = make_float2(acc[mt][nt][2] + b0, acc[mt][nt][3] + b1);
                *(float2*)(Y + (size_t)r1 * DD + c) = o;
            }
        }
    }
}

// ---------------- BatchNorm --------------------------------------------------
__global__ void stats_kernel(const float* __restrict__ Y) {
    int c = threadIdx.x;
    float s = 0.f, sq = 0.f;
    for (int r = blockIdx.x; r < NN; r += gridDim.x) {
        float v = __ldg(&Y[(size_t)r * DD + c]);
        s += v;
        sq += v * v;
    }
    atomicAdd(&g_stats[c], s);
    atomicAdd(&g_stats[DD + c], sq);
}

__global__ void finalize_kernel(const float* __restrict__ gamma,
                                const float* __restrict__ beta) {
    int c = threadIdx.x;
    float m = g_stats[c] * (1.0f / NN);
    float var = g_stats[DD + c] * (1.0f / NN) - m * m;
    float sc = __ldg(&gamma[c]) * rsqrtf(var + EPS);
    g_stats[2 * DD + c] = sc;
    g_stats[3 * DD + c] = __ldg(&beta[c]) - m * sc;
}

__global__ void apply_kernel(float* __restrict__ Y, int relu) {
    int i = blockIdx.x * blockDim.x + threadIdx.x;
    if (i >= NN * (DD / 4)) return;
    float4 v = ((float4*)Y)[i];
    int c = (i & (DD / 4 - 1)) * 4;
    float s0 = g_stats[2 * DD + c + 0], b0 = g_stats[3 * DD + c + 0];
    float s1 = g_stats[2 * DD + c + 1], b1 = g_stats[3 * DD + c + 1];
    float s2 = g_stats[2 * DD + c + 2], b2 = g_stats[3 * DD + c + 2];
    float s3 = g_stats[2 * DD + c + 3], b3 = g_stats[3 * DD + c + 3];
    v.x = v.x * s0 + b0;
    v.y = v.y * s1 + b1;
    v.z = v.z * s2 + b2;
    v.w = v.w * s3 + b3;
    if (relu) {
        v.x = fmaxf(v.x, 0.f); v.y = fmaxf(v.y, 0.f);
        v.z = fmaxf(v.z, 0.f); v.w = fmaxf(v.w, 0.f);
    }
    ((float4*)Y)[i] = v;
}

// ---------------- launch ----------------------------------------------------
extern "C" void kernel_launch(void* const* d_in, const int* in_sizes, int n_in,
                              void* d_out, int out_size) {
    const float* x = (const float*)d_in[0];
    const int* ei = (const int*)d_in[1];   // int32 on device (JAX x64 disabled)
    const float* Wl[3] = {(const float*)d_in[2], (const float*)d_in[7], (const float*)d_in[12]};
    const float* bl[3] = {(const float*)d_in[3], (const float*)d_in[8], (const float*)d_in[13]};
    const float* Wr[3] = {(const float*)d_in[4], (const float*)d_in[9], (const float*)d_in[14]};
    const float* gm[3] = {(const float*)d_in[5], (const float*)d_in[10], (const float*)d_in[15]};
    const float* bt[3] = {(const float*)d_in[6], (const float*)d_in[11], (const float*)d_in[16]};
    int E = in_sizes[1] / 2;

    void *p_h0, *p_h1, *p_stats, *p_deg;
    cudaGetSymbolAddress(&p_h0, g_h0);
    cudaGetSymbolAddress(&p_h1, g_h1);
    cudaGetSymbolAddress(&p_stats, g_stats);
    cudaGetSymbolAddress(&p_deg, g_deg);

    // ---- build CSR once per call ----
    const int NB = (NN + 1023) / 1024;  // 49
    zero_i4<<<(12500 + 255) / 256, 256>>>((int*)p_deg, 12500);
    count_kernel<<<(E + 255) / 256, 256>>>(ei, E);
    scan1_kernel<<<NB, 1024>>>();
    scan2_kernel<<<1, 64>>>(NB);
    scan3_kernel<<<NB, 1024>>>();
    fill_kernel<<<(E + 255) / 256, 256>>>(ei, E);

    for (int L = 0; L < 3; L++) {
        const float* Xin = (L == 0) ? x : (L == 1 ? (const float*)p_h0 : (const float*)p_h1);
        float* Y = (L == 0) ? (float*)p_h0 : (L == 1 ? (float*)p_h1 : (float*)d_out);

        gather_kernel<<<(NN * 32 + 255) / 256, 256>>>(Xin);
        prep_w_kernel<<<(K2 * DD + 255) / 256, 256>>>(Wl[L], Wr[L]);
        gemm_kernel<<<(NN + 127) / 128, 128>>>(Xin, bl[L], Y);

        zero_f4<<<1, 64>>>((float*)p_stats, 64);
        stats_kernel<<<512, 128>>>(Y);
        finalize_kernel<<<1, 128>>>(gm[L], bt[L]);
        apply_kernel<<<(NN * DD / 4 + 255) / 256, 256>>>(Y, L < 2 ? 1 : 0);
    }
}

// round 5
// speedup vs baseline: 1.8454x; 1.1411x over previous
#include <cuda_runtime.h>
#include <cstdint>

#define NN 50000
#define DD 128
#define K2 256
#define EE 800000
#define EPS 1e-5f

// ---------------- scratch (device globals) ----------------------------------
__device__ float g_agg[NN * DD];     // mean-aggregated (transformed) features
__device__ float g_h0[NN * DD];      // layer 0 pre-BN output
__device__ float g_h1[NN * DD];      // layer 1 pre-BN output
__device__ float g_Wt[K2 * DD];      // combined transposed weights [k][j]
__device__ float g_stats[4 * DD];    // [sum | sumsq | scale | shift]
__device__ int   g_deg[NN];          // in-degree
__device__ int   g_rowptr[NN + 1];   // CSR row pointers
__device__ int   g_cursor[NN];       // fill cursors
__device__ int   g_col[EE];          // CSR column (source) indices
__device__ int   g_bsum[64];         // scan block sums
__device__ int   g_boff[64];         // scan block offsets

// ---------------- utility ---------------------------------------------------
__global__ void zero_i4(int* __restrict__ p, int n4) {
    int i = blockIdx.x * blockDim.x + threadIdx.x;
    if (i < n4) ((int4*)p)[i] = make_int4(0, 0, 0, 0);
}

// ---------------- CSR build --------------------------------------------------
__global__ void count_kernel(const int* __restrict__ ei, int E) {
    int e = blockIdx.x * blockDim.x + threadIdx.x;
    if (e < E) {
        int d = ei[E + e];
        if (d >= 0 && d < NN) atomicAdd(&g_deg[d], 1);
    }
}

__global__ void scan1_kernel() {
    __shared__ int wsum[32];
    int t = threadIdx.x, b = blockIdx.x;
    int idx = b * 1024 + t;
    int wid = t >> 5, lane = t & 31;
    int v = (idx < NN) ? g_deg[idx] : 0;
    int incl = v;
#pragma unroll
    for (int off = 1; off < 32; off <<= 1) {
        int y = __shfl_up_sync(0xffffffffu, incl, off);
        if (lane >= off) incl += y;
    }
    if (lane == 31) wsum[wid] = incl;
    __syncthreads();
    if (wid == 0) {
        int si = wsum[lane];
#pragma unroll
        for (int off = 1; off < 32; off <<= 1) {
            int y = __shfl_up_sync(0xffffffffu, si, off);
            if (lane >= off) si += y;
        }
        wsum[lane] = si;
    }
    __syncthreads();
    int woff = (wid > 0) ? wsum[wid - 1] : 0;
    if (idx < NN) g_rowptr[idx] = woff + incl - v;
    if (t == 0) g_bsum[b] = wsum[31];
}

__global__ void scan2_kernel(int nb) {
    __shared__ int sh[64];
    int t = threadIdx.x;
    sh[t] = (t < nb) ? g_bsum[t] : 0;
    __syncthreads();
#pragma unroll
    for (int off = 1; off < 64; off <<= 1) {
        int y = (t >= off) ? sh[t - off] : 0;
        __syncthreads();
        sh[t] += y;
        __syncthreads();
    }
    if (t < nb) g_boff[t] = sh[t] - g_bsum[t];
    if (t == 0) g_rowptr[NN] = sh[63];
}

__global__ void scan3_kernel() {
    int idx = blockIdx.x * 1024 + threadIdx.x;
    if (idx < NN) {
        int r = g_rowptr[idx] + g_boff[blockIdx.x];
        g_rowptr[idx] = r;
        g_cursor[idx] = r;
    }
}

__global__ void fill_kernel(const int* __restrict__ ei, int E) {
    int e = blockIdx.x * blockDim.x + threadIdx.x;
    if (e < E) {
        int s = ei[e];
        int d = ei[E + e];
        if (d >= 0 && d < NN) {
            int pos = atomicAdd(&g_cursor[d], 1);
            g_col[pos] = s;
        }
    }
}

// ---------------- mean gather with optional fused BN+ReLU on inputs ---------
template <int XFORM>
__global__ void gather_kernel(const float* __restrict__ x) {
    int w = (blockIdx.x * blockDim.x + threadIdx.x) >> 5;
    int lane = threadIdx.x & 31;
    if (w >= NN) return;
    float4 s4 = make_float4(1.f, 1.f, 1.f, 1.f);
    float4 b4 = make_float4(0.f, 0.f, 0.f, 0.f);
    if (XFORM) {
        s4 = ((const float4*)(g_stats + 2 * DD))[lane];
        b4 = ((const float4*)(g_stats + 3 * DD))[lane];
    }
    int start = g_rowptr[w], end = g_rowptr[w + 1];
    float4 acc = make_float4(0.f, 0.f, 0.f, 0.f);
    int i = start;
    for (; i + 3 < end; i += 4) {
        int s0 = __ldg(&g_col[i + 0]);
        int s1 = __ldg(&g_col[i + 1]);
        int s2 = __ldg(&g_col[i + 2]);
        int s3 = __ldg(&g_col[i + 3]);
        float4 v0 = __ldg((const float4*)(x + (size_t)s0 * DD) + lane);
        float4 v1 = __ldg((const float4*)(x + (size_t)s1 * DD) + lane);
        float4 v2 = __ldg((const float4*)(x + (size_t)s2 * DD) + lane);
        float4 v3 = __ldg((const float4*)(x + (size_t)s3 * DD) + lane);
        if (XFORM) {
            v0.x = fmaxf(fmaf(v0.x, s4.x, b4.x), 0.f); v0.y = fmaxf(fmaf(v0.y, s4.y, b4.y), 0.f);
            v0.z = fmaxf(fmaf(v0.z, s4.z, b4.z), 0.f); v0.w = fmaxf(fmaf(v0.w, s4.w, b4.w), 0.f);
            v1.x = fmaxf(fmaf(v1.x, s4.x, b4.x), 0.f); v1.y = fmaxf(fmaf(v1.y, s4.y, b4.y), 0.f);
            v1.z = fmaxf(fmaf(v1.z, s4.z, b4.z), 0.f); v1.w = fmaxf(fmaf(v1.w, s4.w, b4.w), 0.f);
            v2.x = fmaxf(fmaf(v2.x, s4.x, b4.x), 0.f); v2.y = fmaxf(fmaf(v2.y, s4.y, b4.y), 0.f);
            v2.z = fmaxf(fmaf(v2.z, s4.z, b4.z), 0.f); v2.w = fmaxf(fmaf(v2.w, s4.w, b4.w), 0.f);
            v3.x = fmaxf(fmaf(v3.x, s4.x, b4.x), 0.f); v3.y = fmaxf(fmaf(v3.y, s4.y, b4.y), 0.f);
            v3.z = fmaxf(fmaf(v3.z, s4.z, b4.z), 0.f); v3.w = fmaxf(fmaf(v3.w, s4.w, b4.w), 0.f);
        }
        acc.x += (v0.x + v1.x) + (v2.x + v3.x);
        acc.y += (v0.y + v1.y) + (v2.y + v3.y);
        acc.z += (v0.z + v1.z) + (v2.z + v3.z);
        acc.w += (v0.w + v1.w) + (v2.w + v3.w);
    }
    for (; i < end; i++) {
        int s = __ldg(&g_col[i]);
        float4 v = __ldg((const float4*)(x + (size_t)s * DD) + lane);
        if (XFORM) {
            v.x = fmaxf(fmaf(v.x, s4.x, b4.x), 0.f); v.y = fmaxf(fmaf(v.y, s4.y, b4.y), 0.f);
            v.z = fmaxf(fmaf(v.z, s4.z, b4.z), 0.f); v.w = fmaxf(fmaf(v.w, s4.w, b4.w), 0.f);
        }
        acc.x += v.x; acc.y += v.y; acc.z += v.z; acc.w += v.w;
    }
    float sc = 1.0f / fmaxf((float)(end - start), 1.0f);
    acc.x *= sc; acc.y *= sc; acc.z *= sc; acc.w *= sc;
    ((float4*)(g_agg + (size_t)w * DD))[lane] = acc;
}

// ---------------- weight prep (+ zero BN accumulators) ----------------------
__global__ void prep_w_kernel(const float* __restrict__ Wl,
                              const float* __restrict__ Wr) {
    int i = blockIdx.x * blockDim.x + threadIdx.x;
    if (blockIdx.x == 0 && threadIdx.x < 2 * DD) g_stats[threadIdx.x] = 0.f;
    if (i >= K2 * DD) return;
    int k = i >> 7, j = i & 127;
    g_Wt[i] = (k < DD) ? __ldg(&Wl[j * DD + k]) : __ldg(&Wr[j * DD + (k - DD)]);
}

// ---------------- 3xTF32 tensor-core GEMM + fused BN stats ------------------
#define ASTRIDE 20
#define BSTRIDE 136

__device__ __forceinline__ void split_tf32(float v, uint32_t& hi, uint32_t& lo) {
    asm("cvt.rna.tf32.f32 %0, %1;" : "=r"(hi) : "f"(v));
    float l = v - __uint_as_float(hi);
    asm("cvt.rna.tf32.f32 %0, %1;" : "=r"(lo) : "f"(l));
}

__device__ __forceinline__ void mma_tf32(float* d, uint32_t a0, uint32_t a1,
                                         uint32_t a2, uint32_t a3,
                                         uint32_t b0, uint32_t b1) {
    asm volatile(
        "mma.sync.aligned.m16n8k8.row.col.f32.tf32.tf32.f32 "
        "{%0,%1,%2,%3},{%4,%5,%6,%7},{%8,%9},{%0,%1,%2,%3};"
        : "+f"(d[0]), "+f"(d[1]), "+f"(d[2]), "+f"(d[3])
        : "r"(a0), "r"(a1), "r"(a2), "r"(a3), "r"(b0), "r"(b1));
}

template <int XFORM>
__global__ __launch_bounds__(128, 2)
void gemm_kernel(const float* __restrict__ Xin,
                 const float* __restrict__ bias,
                 float* __restrict__ Y) {
    __shared__ float As_hi[128 * ASTRIDE];
    __shared__ float As_lo[128 * ASTRIDE];
    __shared__ float Bs_hi[16 * BSTRIDE];
    __shared__ float Bs_lo[16 * BSTRIDE];
    __shared__ float bias_s[128];

    int tid = threadIdx.x;
    int brow = blockIdx.x * 128;
    int wid = tid >> 5, lane = tid & 31;
    int group = lane >> 2, tg = lane & 3;
    int warp_m = (wid >> 1) * 64, warp_n = (wid & 1) * 64;

    if (tid < 128) bias_s[tid] = __ldg(&bias[tid]);

    float acc[4][8][4];
#pragma unroll
    for (int mt = 0; mt < 4; mt++)
#pragma unroll
        for (int nt = 0; nt < 8; nt++)
#pragma unroll
            for (int c = 0; c < 4; c++) acc[mt][nt][c] = 0.f;

    float4 pa[4], pb[4];

    auto load_tiles = [&](int kc) {
        const float* srcp = (kc < DD) ? (g_agg + kc) : (Xin + (kc - DD));
#pragma unroll
        for (int i = 0; i < 4; i++) {
            int l = tid + i * 128;
            int row = l >> 2, kq = l & 3;
            int r = brow + row;
            pa[i] = (r < NN) ? __ldg((const float4*)(srcp + (size_t)r * DD) + kq)
                             : make_float4(0.f, 0.f, 0.f, 0.f);
            if (XFORM && kc >= DD) {
                int kg = (kc - DD) + kq * 4;
                float4 s4 = *(const float4*)(g_stats + 2 * DD + kg);
                float4 b4 = *(const float4*)(g_stats + 3 * DD + kg);
                pa[i].x = fmaxf(fmaf(pa[i].x, s4.x, b4.x), 0.f);
                pa[i].y = fmaxf(fmaf(pa[i].y, s4.y, b4.y), 0.f);
                pa[i].z = fmaxf(fmaf(pa[i].z, s4.z, b4.z), 0.f);
                pa[i].w = fmaxf(fmaf(pa[i].w, s4.w, b4.w), 0.f);
            }
        }
#pragma unroll
        for (int i = 0; i < 4; i++) {
            int l = tid + i * 128;
            int k = l >> 5, j4 = l & 31;
            pb[i] = __ldg((const float4*)(g_Wt + (size_t)(kc + k) * DD) + j4);
        }
    };

    auto store_tiles = [&]() {
#pragma unroll
        for (int i = 0; i < 4; i++) {
            int l = tid + i * 128;
            int row = l >> 2, kq = l & 3;
            float vv[4] = {pa[i].x, pa[i].y, pa[i].z, pa[i].w};
#pragma unroll
            for (int c = 0; c < 4; c++) {
                uint32_t h, lo;
                split_tf32(vv[c], h, lo);
                As_hi[row * ASTRIDE + kq * 4 + c] = __uint_as_float(h);
                As_lo[row * ASTRIDE + kq * 4 + c] = __uint_as_float(lo);
            }
        }
#pragma unroll
        for (int i = 0; i < 4; i++) {
            int l = tid + i * 128;
            int k = l >> 5, j4 = l & 31;
            float vv[4] = {pb[i].x, pb[i].y, pb[i].z, pb[i].w};
#pragma unroll
            for (int c = 0; c < 4; c++) {
                uint32_t h, lo;
                split_tf32(vv[c], h, lo);
                Bs_hi[k * BSTRIDE + j4 * 4 + c] = __uint_as_float(h);
                Bs_lo[k * BSTRIDE + j4 * 4 + c] = __uint_as_float(lo);
            }
        }
    };

    load_tiles(0);

    for (int kc = 0; kc < K2; kc += 16) {
        store_tiles();
        __syncthreads();
        if (kc + 16 < K2) load_tiles(kc + 16);

#pragma unroll
        for (int k0 = 0; k0 < 16; k0 += 8) {
            uint32_t bh0[8], bh1[8], bl0[8], bl1[8];
#pragma unroll
            for (int nt = 0; nt < 8; nt++) {
                int n = warp_n + nt * 8 + group;
                bh0[nt] = __float_as_uint(Bs_hi[(k0 + tg) * BSTRIDE + n]);
                bh1[nt] = __float_as_uint(Bs_hi[(k0 + tg + 4) * BSTRIDE + n]);
                bl0[nt] = __float_as_uint(Bs_lo[(k0 + tg) * BSTRIDE + n]);
                bl1[nt] = __float_as_uint(Bs_lo[(k0 + tg + 4) * BSTRIDE + n]);
            }
#pragma unroll
            for (int mt = 0; mt < 4; mt++) {
                int m = warp_m + mt * 16;
                uint32_t ah0 = __float_as_uint(As_hi[(m + group) * ASTRIDE + k0 + tg]);
                uint32_t ah1 = __float_as_uint(As_hi[(m + group + 8) * ASTRIDE + k0 + tg]);
                uint32_t ah2 = __float_as_uint(As_hi[(m + group) * ASTRIDE + k0 + tg + 4]);
                uint32_t ah3 = __float_as_uint(As_hi[(m + group + 8) * ASTRIDE + k0 + tg + 4]);
                uint32_t al0 = __float_as_uint(As_lo[(m + group) * ASTRIDE + k0 + tg]);
                uint32_t al1 = __float_as_uint(As_lo[(m + group + 8) * ASTRIDE + k0 + tg]);
                uint32_t al2 = __float_as_uint(As_lo[(m + group) * ASTRIDE + k0 + tg + 4]);
                uint32_t al3 = __float_as_uint(As_lo[(m + group + 8) * ASTRIDE + k0 + tg + 4]);
#pragma unroll
                for (int nt = 0; nt < 8; nt++) {
                    mma_tf32(acc[mt][nt], ah0, ah1, ah2, ah3, bh0[nt], bh1[nt]);
                    mma_tf32(acc[mt][nt], al0, al1, al2, al3, bh0[nt], bh1[nt]);
                    mma_tf32(acc[mt][nt], ah0, ah1, ah2, ah3, bl0[nt], bl1[nt]);
                }
            }
        }
        __syncthreads();
    }

    // epilogue: bias + store + fused BN partial stats
    float cs[16], cq[16];
#pragma unroll
    for (int i = 0; i < 16; i++) { cs[i] = 0.f; cq[i] = 0.f; }

#pragma unroll
    for (int mt = 0; mt < 4; mt++) {
        int r0 = brow + warp_m + mt * 16 + group;
        int r1 = r0 + 8;
#pragma unroll
        for (int nt = 0; nt < 8; nt++) {
            int c = warp_n + nt * 8 + 2 * tg;
            float b0 = bias_s[c], b1 = bias_s[c + 1];
            float o0 = acc[mt][nt][0] + b0, o1 = acc[mt][nt][1] + b1;
            float o2 = acc[mt][nt][2] + b0, o3 = acc[mt][nt][3] + b1;
            if (r0 < NN) {
                *(float2*)(Y + (size_t)r0 * DD + c) = make_float2(o0, o1);
                cs[nt * 2 + 0] += o0; cq[nt * 2 + 0] += o0 * o0;
                cs[nt * 2 + 1] += o1; cq[nt * 2 + 1] += o1 * o1;
            }
            if (r1 < NN) {
                *(float2*)(Y + (size_t)r1 * DD + c) = make_float2(o2, o3);
                cs[nt * 2 + 0] += o2; cq[nt * 2 + 0] += o2 * o2;
                cs[nt * 2 + 1] += o3; cq[nt * 2 + 1] += o3 * o3;
            }
        }
    }
    // reduce across the 8 row-groups (lanes with identical tg)
#pragma unroll
    for (int i = 0; i < 16; i++) {
#pragma unroll
        for (int off = 4; off < 32; off <<= 1) {
            cs[i] += __shfl_xor_sync(0xffffffffu, cs[i], off);
            cq[i] += __shfl_xor_sync(0xffffffffu, cq[i], off);
        }
    }
    if (group == 0) {
#pragma unroll
        for (int i = 0; i < 16; i++) {
            int c = warp_n + (i >> 1) * 8 + 2 * tg + (i & 1);
            atomicAdd(&g_stats[c], cs[i]);
            atomicAdd(&g_stats[DD + c], cq[i]);
        }
    }
}

// ---------------- BN finalize + final apply ----------------------------------
__global__ void finalize_kernel(const float* __restrict__ gamma,
                                const float* __restrict__ beta) {
    int c = threadIdx.x;
    float m = g_stats[c] * (1.0f / NN);
    float var = g_stats[DD + c] * (1.0f / NN) - m * m;
    float sc = __ldg(&gamma[c]) * rsqrtf(var + EPS);
    g_stats[2 * DD + c] = sc;
    g_stats[3 * DD + c] = __ldg(&beta[c]) - m * sc;
}

__global__ void apply_kernel(float* __restrict__ Y) {
    int i = blockIdx.x * blockDim.x + threadIdx.x;
    if (i >= NN * (DD / 4)) return;
    float4 v = ((float4*)Y)[i];
    int c = (i & (DD / 4 - 1)) * 4;
    float s0 = g_stats[2 * DD + c + 0], b0 = g_stats[3 * DD + c + 0];
    float s1 = g_stats[2 * DD + c + 1], b1 = g_stats[3 * DD + c + 1];
    float s2 = g_stats[2 * DD + c + 2], b2 = g_stats[3 * DD + c + 2];
    float s3 = g_stats[2 * DD + c + 3], b3 = g_stats[3 * DD + c + 3];
    v.x = v.x * s0 + b0;
    v.y = v.y * s1 + b1;
    v.z = v.z * s2 + b2;
    v.w = v.w * s3 + b3;
    ((float4*)Y)[i] = v;
}

// ---------------- launch ----------------------------------------------------
extern "C" void kernel_launch(void* const* d_in, const int* in_sizes, int n_in,
                              void* d_out, int out_size) {
    const float* x = (const float*)d_in[0];
    const int* ei = (const int*)d_in[1];
    const float* Wl[3] = {(const float*)d_in[2], (const float*)d_in[7], (const float*)d_in[12]};
    const float* bl[3] = {(const float*)d_in[3], (const float*)d_in[8], (const float*)d_in[13]};
    const float* Wr[3] = {(const float*)d_in[4], (const float*)d_in[9], (const float*)d_in[14]};
    const float* gm[3] = {(const float*)d_in[5], (const float*)d_in[10], (const float*)d_in[15]};
    const float* bt[3] = {(const float*)d_in[6], (const float*)d_in[11], (const float*)d_in[16]};
    int E = in_sizes[1] / 2;

    void *p_h0, *p_h1, *p_deg;
    cudaGetSymbolAddress(&p_h0, g_h0);
    cudaGetSymbolAddress(&p_h1, g_h1);
    cudaGetSymbolAddress(&p_deg, g_deg);

    // ---- build CSR once per call ----
    const int NB = (NN + 1023) / 1024;  // 49
    zero_i4<<<(12500 + 255) / 256, 256>>>((int*)p_deg, 12500);
    count_kernel<<<(E + 255) / 256, 256>>>(ei, E);
    scan1_kernel<<<NB, 1024>>>();
    scan2_kernel<<<1, 64>>>(NB);
    scan3_kernel<<<NB, 1024>>>();
    fill_kernel<<<(E + 255) / 256, 256>>>(ei, E);

    const int GB = (NN * 32 + 255) / 256;
    const int WB = (K2 * DD + 255) / 256;
    const int MB = (NN + 127) / 128;

    for (int L = 0; L < 3; L++) {
        const float* Xin = (L == 0) ? x : (L == 1 ? (const float*)p_h0 : (const float*)p_h1);
        float* Y = (L == 0) ? (float*)p_h0 : (L == 1 ? (float*)p_h1 : (float*)d_out);

        if (L == 0) gather_kernel<0><<<GB, 256>>>(Xin);
        else        gather_kernel<1><<<GB, 256>>>(Xin);

        prep_w_kernel<<<WB, 256>>>(Wl[L], Wr[L]);  // also zeroes BN accumulators

        if (L == 0) gemm_kernel<0><<<MB, 128>>>(Xin, bl[L], Y);
        else        gemm_kernel<1><<<MB, 128>>>(Xin, bl[L], Y);

        finalize_kernel<<<1, 128>>>(gm[L], bt[L]);
    }
    apply_kernel<<<(NN * DD / 4 + 255) / 256, 256>>>((float*)d_out);
}

// round 6
// speedup vs baseline: 1.9270x; 1.0442x over previous
#include <cuda_runtime.h>
#include <cuda_fp16.h>
#include <cstdint>
#include <type_traits>

#define NN 50000
#define DD 128
#define K2 256
#define EE 800000
#define EPS 1e-5f

// ---------------- scratch (device globals) ----------------------------------
__device__ float  g_agg[NN * DD];      // mean-aggregated (transformed) features, fp32
__device__ __half g_h0[NN * DD];       // layer 0 pre-BN output (fp16)
__device__ __half g_h1[NN * DD];       // layer 1 pre-BN output (fp16)
__device__ float  g_Wt3[3 * K2 * DD];  // combined transposed weights per layer
__device__ float  g_stats[4 * DD];     // [sum | sumsq | scale | shift]
__device__ int    g_deg[NN];
__device__ int    g_rowptr[NN + 1];
__device__ int    g_cursor[NN];
__device__ int    g_col[EE];
__device__ int    g_bsum[64];
__device__ int    g_boff[64];

// ---------------- utility ---------------------------------------------------
__global__ void zero_i4(int* __restrict__ p, int n4) {
    int i = blockIdx.x * blockDim.x + threadIdx.x;
    if (i < n4) ((int4*)p)[i] = make_int4(0, 0, 0, 0);
}

// ---------------- CSR build --------------------------------------------------
__global__ void count_kernel(const int* __restrict__ ei, int E) {
    int e = blockIdx.x * blockDim.x + threadIdx.x;
    if (e < E) {
        int d = ei[E + e];
        if (d >= 0 && d < NN) atomicAdd(&g_deg[d], 1);
    }
}

__global__ void scan1_kernel() {
    __shared__ int wsum[32];
    int t = threadIdx.x, b = blockIdx.x;
    int idx = b * 1024 + t;
    int wid = t >> 5, lane = t & 31;
    int v = (idx < NN) ? g_deg[idx] : 0;
    int incl = v;
#pragma unroll
    for (int off = 1; off < 32; off <<= 1) {
        int y = __shfl_up_sync(0xffffffffu, incl, off);
        if (lane >= off) incl += y;
    }
    if (lane == 31) wsum[wid] = incl;
    __syncthreads();
    if (wid == 0) {
        int si = wsum[lane];
#pragma unroll
        for (int off = 1; off < 32; off <<= 1) {
            int y = __shfl_up_sync(0xffffffffu, si, off);
            if (lane >= off) si += y;
        }
        wsum[lane] = si;
    }
    __syncthreads();
    int woff = (wid > 0) ? wsum[wid - 1] : 0;
    if (idx < NN) g_rowptr[idx] = woff + incl - v;
    if (t == 0) g_bsum[b] = wsum[31];
}

__global__ void scan2_kernel(int nb) {
    __shared__ int sh[64];
    int t = threadIdx.x;
    sh[t] = (t < nb) ? g_bsum[t] : 0;
    __syncthreads();
#pragma unroll
    for (int off = 1; off < 64; off <<= 1) {
        int y = (t >= off) ? sh[t - off] : 0;
        __syncthreads();
        sh[t] += y;
        __syncthreads();
    }
    if (t < nb) g_boff[t] = sh[t] - g_bsum[t];
    if (t == 0) g_rowptr[NN] = sh[63];
}

__global__ void scan3_kernel() {
    int idx = blockIdx.x * 1024 + threadIdx.x;
    if (idx < NN) {
        int r = g_rowptr[idx] + g_boff[blockIdx.x];
        g_rowptr[idx] = r;
        g_cursor[idx] = r;
    }
}

__global__ void fill_kernel(const int* __restrict__ ei, int E) {
    int e = blockIdx.x * blockDim.x + threadIdx.x;
    if (e < E) {
        int s = ei[e];
        int d = ei[E + e];
        if (d >= 0 && d < NN) {
            int pos = atomicAdd(&g_cursor[d], 1);
            g_col[pos] = s;
        }
    }
}

// ---------------- gather (fp32 input, layer 0): also zeroes BN accumulators --
__global__ void gather_f32(const float* __restrict__ x) {
    if (blockIdx.x == 0 && threadIdx.x < 2 * DD) g_stats[threadIdx.x] = 0.f;
    int w = (blockIdx.x * blockDim.x + threadIdx.x) >> 5;
    int lane = threadIdx.x & 31;
    if (w >= NN) return;
    int start = g_rowptr[w], end = g_rowptr[w + 1];
    float4 acc = make_float4(0.f, 0.f, 0.f, 0.f);
    int i = start;
    for (; i + 3 < end; i += 4) {
        int s0 = __ldg(&g_col[i + 0]);
        int s1 = __ldg(&g_col[i + 1]);
        int s2 = __ldg(&g_col[i + 2]);
        int s3 = __ldg(&g_col[i + 3]);
        float4 v0 = __ldg((const float4*)(x + (size_t)s0 * DD) + lane);
        float4 v1 = __ldg((const float4*)(x + (size_t)s1 * DD) + lane);
        float4 v2 = __ldg((const float4*)(x + (size_t)s2 * DD) + lane);
        float4 v3 = __ldg((const float4*)(x + (size_t)s3 * DD) + lane);
        acc.x += (v0.x + v1.x) + (v2.x + v3.x);
        acc.y += (v0.y + v1.y) + (v2.y + v3.y);
        acc.z += (v0.z + v1.z) + (v2.z + v3.z);
        acc.w += (v0.w + v1.w) + (v2.w + v3.w);
    }
    for (; i < end; i++) {
        int s = __ldg(&g_col[i]);
        float4 v = __ldg((const float4*)(x + (size_t)s * DD) + lane);
        acc.x += v.x; acc.y += v.y; acc.z += v.z; acc.w += v.w;
    }
    float sc = 1.0f / fmaxf((float)(end - start), 1.0f);
    acc.x *= sc; acc.y *= sc; acc.z *= sc; acc.w *= sc;
    ((float4*)(g_agg + (size_t)w * DD))[lane] = acc;
}

// ---------------- gather (fp16 input + fused BN+ReLU), layers 1/2 -----------
__global__ void gather_f16(const __half* __restrict__ x) {
    if (blockIdx.x == 0 && threadIdx.x < 2 * DD) g_stats[threadIdx.x] = 0.f;
    int w = (blockIdx.x * blockDim.x + threadIdx.x) >> 5;
    int lane = threadIdx.x & 31;
    if (w >= NN) return;
    float4 s4 = ((const float4*)(g_stats + 2 * DD))[lane];
    float4 b4 = ((const float4*)(g_stats + 3 * DD))[lane];
    int start = g_rowptr[w], end = g_rowptr[w + 1];
    float4 acc = make_float4(0.f, 0.f, 0.f, 0.f);

    auto addv = [&](uint2 raw) {
        __half2 h0 = *reinterpret_cast<__half2*>(&raw.x);
        __half2 h1 = *reinterpret_cast<__half2*>(&raw.y);
        float2 f0 = __half22float2(h0);
        float2 f1 = __half22float2(h1);
        acc.x += fmaxf(fmaf(f0.x, s4.x, b4.x), 0.f);
        acc.y += fmaxf(fmaf(f0.y, s4.y, b4.y), 0.f);
        acc.z += fmaxf(fmaf(f1.x, s4.z, b4.z), 0.f);
        acc.w += fmaxf(fmaf(f1.y, s4.w, b4.w), 0.f);
    };

    int i = start;
    for (; i + 3 < end; i += 4) {
        int s0 = __ldg(&g_col[i + 0]);
        int s1 = __ldg(&g_col[i + 1]);
        int s2 = __ldg(&g_col[i + 2]);
        int s3 = __ldg(&g_col[i + 3]);
        uint2 r0 = __ldg((const uint2*)(x + (size_t)s0 * DD) + lane);
        uint2 r1 = __ldg((const uint2*)(x + (size_t)s1 * DD) + lane);
        uint2 r2 = __ldg((const uint2*)(x + (size_t)s2 * DD) + lane);
        uint2 r3 = __ldg((const uint2*)(x + (size_t)s3 * DD) + lane);
        addv(r0); addv(r1); addv(r2); addv(r3);
    }
    for (; i < end; i++) {
        int s = __ldg(&g_col[i]);
        addv(__ldg((const uint2*)(x + (size_t)s * DD) + lane));
    }
    float sc = 1.0f / fmaxf((float)(end - start), 1.0f);
    acc.x *= sc; acc.y *= sc; acc.z *= sc; acc.w *= sc;
    ((float4*)(g_agg + (size_t)w * DD))[lane] = acc;
}

// ---------------- weight prep: all 3 layers in one launch --------------------
__global__ void prep_w_all(const float* __restrict__ Wl0, const float* __restrict__ Wr0,
                           const float* __restrict__ Wl1, const float* __restrict__ Wr1,
                           const float* __restrict__ Wl2, const float* __restrict__ Wr2) {
    int i = blockIdx.x * blockDim.x + threadIdx.x;
    if (i >= 3 * K2 * DD) return;
    int L = i / (K2 * DD);
    int r = i - L * (K2 * DD);
    int k = r >> 7, j = r & 127;
    const float* Wl = (L == 0) ? Wl0 : (L == 1 ? Wl1 : Wl2);
    const float* Wr = (L == 0) ? Wr0 : (L == 1 ? Wr1 : Wr2);
    g_Wt3[i] = (k < DD) ? __ldg(&Wl[j * DD + k]) : __ldg(&Wr[j * DD + (k - DD)]);
}

// ---------------- 3xTF32 tensor-core GEMM + fused BN stats ------------------
#define ASTRIDE 20
#define BSTRIDE 136

__device__ __forceinline__ void split_tf32(float v, uint32_t& hi, uint32_t& lo) {
    asm("cvt.rna.tf32.f32 %0, %1;" : "=r"(hi) : "f"(v));
    float l = v - __uint_as_float(hi);
    asm("cvt.rna.tf32.f32 %0, %1;" : "=r"(lo) : "f"(l));
}

__device__ __forceinline__ void mma_tf32(float* d, uint32_t a0, uint32_t a1,
                                         uint32_t a2, uint32_t a3,
                                         uint32_t b0, uint32_t b1) {
    asm volatile(
        "mma.sync.aligned.m16n8k8.row.col.f32.tf32.tf32.f32 "
        "{%0,%1,%2,%3},{%4,%5,%6,%7},{%8,%9},{%0,%1,%2,%3};"
        : "+f"(d[0]), "+f"(d[1]), "+f"(d[2]), "+f"(d[3])
        : "r"(a0), "r"(a1), "r"(a2), "r"(a3), "r"(b0), "r"(b1));
}

// TI: input type of Xin (float or __half); XFORM: apply BN+ReLU to x-half;
// TO: output type of Y (float or __half)
template <typename TI, int XFORM, typename TO>
__global__ __launch_bounds__(128, 2)
void gemm_kernel(const TI* __restrict__ Xin,
                 const float* __restrict__ Wt,
                 const float* __restrict__ bias,
                 TO* __restrict__ Y) {
    __shared__ float As_hi[128 * ASTRIDE];
    __shared__ float As_lo[128 * ASTRIDE];
    __shared__ float Bs_hi[16 * BSTRIDE];
    __shared__ float Bs_lo[16 * BSTRIDE];
    __shared__ float bias_s[128];

    int tid = threadIdx.x;
    int brow = blockIdx.x * 128;
    int wid = tid >> 5, lane = tid & 31;
    int group = lane >> 2, tg = lane & 3;
    int warp_m = (wid >> 1) * 64, warp_n = (wid & 1) * 64;

    if (tid < 128) bias_s[tid] = __ldg(&bias[tid]);

    float acc[4][8][4];
#pragma unroll
    for (int mt = 0; mt < 4; mt++)
#pragma unroll
        for (int nt = 0; nt < 8; nt++)
#pragma unroll
            for (int c = 0; c < 4; c++) acc[mt][nt][c] = 0.f;

    float4 pa[4], pb[4];

    auto load_tiles = [&](int kc) {
#pragma unroll
        for (int i = 0; i < 4; i++) {
            int l = tid + i * 128;
            int row = l >> 2, kq = l & 3;
            int r = brow + row;
            float4 v = make_float4(0.f, 0.f, 0.f, 0.f);
            if (r < NN) {
                if (kc < DD) {
                    v = __ldg((const float4*)(g_agg + (size_t)r * DD + kc) + kq);
                } else {
                    int kg = (kc - DD) + kq * 4;
                    if constexpr (std::is_same_v<TI, __half>) {
                        uint2 raw = __ldg((const uint2*)(Xin + (size_t)r * DD + kg));
                        __half2 h0 = *reinterpret_cast<__half2*>(&raw.x);
                        __half2 h1 = *reinterpret_cast<__half2*>(&raw.y);
                        float2 f0 = __half22float2(h0);
                        float2 f1 = __half22float2(h1);
                        v = make_float4(f0.x, f0.y, f1.x, f1.y);
                    } else {
                        v = __ldg((const float4*)(Xin + (size_t)r * DD + kg));
                    }
                    if (XFORM) {
                        float4 s4 = *(const float4*)(g_stats + 2 * DD + kg);
                        float4 b4 = *(const float4*)(g_stats + 3 * DD + kg);
                        v.x = fmaxf(fmaf(v.x, s4.x, b4.x), 0.f);
                        v.y = fmaxf(fmaf(v.y, s4.y, b4.y), 0.f);
                        v.z = fmaxf(fmaf(v.z, s4.z, b4.z), 0.f);
                        v.w = fmaxf(fmaf(v.w, s4.w, b4.w), 0.f);
                    }
                }
            }
            pa[i] = v;
        }
#pragma unroll
        for (int i = 0; i < 4; i++) {
            int l = tid + i * 128;
            int k = l >> 5, j4 = l & 31;
            pb[i] = __ldg((const float4*)(Wt + (size_t)(kc + k) * DD) + j4);
        }
    };

    auto store_tiles = [&]() {
#pragma unroll
        for (int i = 0; i < 4; i++) {
            int l = tid + i * 128;
            int row = l >> 2, kq = l & 3;
            float vv[4] = {pa[i].x, pa[i].y, pa[i].z, pa[i].w};
#pragma unroll
            for (int c = 0; c < 4; c++) {
                uint32_t h, lo;
                split_tf32(vv[c], h, lo);
                As_hi[row * ASTRIDE + kq * 4 + c] = __uint_as_float(h);
                As_lo[row * ASTRIDE + kq * 4 + c] = __uint_as_float(lo);
            }
        }
#pragma unroll
        for (int i = 0; i < 4; i++) {
            int l = tid + i * 128;
            int k = l >> 5, j4 = l & 31;
            float vv[4] = {pb[i].x, pb[i].y, pb[i].z, pb[i].w};
#pragma unroll
            for (int c = 0; c < 4; c++) {
                uint32_t h, lo;
                split_tf32(vv[c], h, lo);
                Bs_hi[k * BSTRIDE + j4 * 4 + c] = __uint_as_float(h);
                Bs_lo[k * BSTRIDE + j4 * 4 + c] = __uint_as_float(lo);
            }
        }
    };

    load_tiles(0);

    for (int kc = 0; kc < K2; kc += 16) {
        store_tiles();
        __syncthreads();
        if (kc + 16 < K2) load_tiles(kc + 16);

#pragma unroll
        for (int k0 = 0; k0 < 16; k0 += 8) {
            uint32_t bh0[8], bh1[8], bl0[8], bl1[8];
#pragma unroll
            for (int nt = 0; nt < 8; nt++) {
                int n = warp_n + nt * 8 + group;
                bh0[nt] = __float_as_uint(Bs_hi[(k0 + tg) * BSTRIDE + n]);
                bh1[nt] = __float_as_uint(Bs_hi[(k0 + tg + 4) * BSTRIDE + n]);
                bl0[nt] = __float_as_uint(Bs_lo[(k0 + tg) * BSTRIDE + n]);
                bl1[nt] = __float_as_uint(Bs_lo[(k0 + tg + 4) * BSTRIDE + n]);
            }
#pragma unroll
            for (int mt = 0; mt < 4; mt++) {
                int m = warp_m + mt * 16;
                uint32_t ah0 = __float_as_uint(As_hi[(m + group) * ASTRIDE + k0 + tg]);
                uint32_t ah1 = __float_as_uint(As_hi[(m + group + 8) * ASTRIDE + k0 + tg]);
                uint32_t ah2 = __float_as_uint(As_hi[(m + group) * ASTRIDE + k0 + tg + 4]);
                uint32_t ah3 = __float_as_uint(As_hi[(m + group + 8) * ASTRIDE + k0 + tg + 4]);
                uint32_t al0 = __float_as_uint(As_lo[(m + group) * ASTRIDE + k0 + tg]);
                uint32_t al1 = __float_as_uint(As_lo[(m + group + 8) * ASTRIDE + k0 + tg]);
                uint32_t al2 = __float_as_uint(As_lo[(m + group) * ASTRIDE + k0 + tg + 4]);
                uint32_t al3 = __float_as_uint(As_lo[(m + group + 8) * ASTRIDE + k0 + tg + 4]);
#pragma unroll
                for (int nt = 0; nt < 8; nt++) {
                    mma_tf32(acc[mt][nt], ah0, ah1, ah2, ah3, bh0[nt], bh1[nt]);
                    mma_tf32(acc[mt][nt], al0, al1, al2, al3, bh0[nt], bh1[nt]);
                    mma_tf32(acc[mt][nt], ah0, ah1, ah2, ah3, bl0[nt], bl1[nt]);
                }
            }
        }
        __syncthreads();
    }

    // epilogue: bias + store + fused BN partial stats
    float cs[16], cq[16];
#pragma unroll
    for (int i = 0; i < 16; i++) { cs[i] = 0.f; cq[i] = 0.f; }

#pragma unroll
    for (int mt = 0; mt < 4; mt++) {
        int r0 = brow + warp_m + mt * 16 + group;
        int r1 = r0 + 8;
#pragma unroll
        for (int nt = 0; nt < 8; nt++) {
            int c = warp_n + nt * 8 + 2 * tg;
            float b0 = bias_s[c], b1 = bias_s[c + 1];
            float o0 = acc[mt][nt][0] + b0, o1 = acc[mt][nt][1] + b1;
            float o2 = acc[mt][nt][2] + b0, o3 = acc[mt][nt][3] + b1;
            if (r0 < NN) {
                if constexpr (std::is_same_v<TO, __half>) {
                    *(__half2*)(Y + (size_t)r0 * DD + c) = __floats2half2_rn(o0, o1);
                } else {
                    *(float2*)(Y + (size_t)r0 * DD + c) = make_float2(o0, o1);
                }
                cs[nt * 2 + 0] += o0; cq[nt * 2 + 0] += o0 * o0;
                cs[nt * 2 + 1] += o1; cq[nt * 2 + 1] += o1 * o1;
            }
            if (r1 < NN) {
                if constexpr (std::is_same_v<TO, __half>) {
                    *(__half2*)(Y + (size_t)r1 * DD + c) = __floats2half2_rn(o2, o3);
                } else {
                    *(float2*)(Y + (size_t)r1 * DD + c) = make_float2(o2, o3);
                }
                cs[nt * 2 + 0] += o2; cq[nt * 2 + 0] += o2 * o2;
                cs[nt * 2 + 1] += o3; cq[nt * 2 + 1] += o3 * o3;
            }
        }
    }
#pragma unroll
    for (int i = 0; i < 16; i++) {
#pragma unroll
        for (int off = 4; off < 32; off <<= 1) {
            cs[i] += __shfl_xor_sync(0xffffffffu, cs[i], off);
            cq[i] += __shfl_xor_sync(0xffffffffu, cq[i], off);
        }
    }
    if (group == 0) {
#pragma unroll
        for (int i = 0; i < 16; i++) {
            int c = warp_n + (i >> 1) * 8 + 2 * tg + (i & 1);
            atomicAdd(&g_stats[c], cs[i]);
            atomicAdd(&g_stats[DD + c], cq[i]);
        }
    }
}

// ---------------- BN finalize + final apply ----------------------------------
__global__ void finalize_kernel(const float* __restrict__ gamma,
                                const float* __restrict__ beta) {
    int c = threadIdx.x;
    float m = g_stats[c] * (1.0f / NN);
    float var = g_stats[DD + c] * (1.0f / NN) - m * m;
    float sc = __ldg(&gamma[c]) * rsqrtf(var + EPS);
    g_stats[2 * DD + c] = sc;
    g_stats[3 * DD + c] = __ldg(&beta[c]) - m * sc;
}

__global__ void apply_kernel(float* __restrict__ Y) {
    int i = blockIdx.x * blockDim.x + threadIdx.x;
    if (i >= NN * (DD / 4)) return;
    float4 v = ((float4*)Y)[i];
    int c = (i & (DD / 4 - 1)) * 4;
    float s0 = g_stats[2 * DD + c + 0], b0 = g_stats[3 * DD + c + 0];
    float s1 = g_stats[2 * DD + c + 1], b1 = g_stats[3 * DD + c + 1];
    float s2 = g_stats[2 * DD + c + 2], b2 = g_stats[3 * DD + c + 2];
    float s3 = g_stats[2 * DD + c + 3], b3 = g_stats[3 * DD + c + 3];
    v.x = v.x * s0 + b0;
    v.y = v.y * s1 + b1;
    v.z = v.z * s2 + b2;
    v.w = v.w * s3 + b3;
    ((float4*)Y)[i] = v;
}

// ---------------- launch ----------------------------------------------------
extern "C" void kernel_launch(void* const* d_in, const int* in_sizes, int n_in,
                              void* d_out, int out_size) {
    const float* x = (const float*)d_in[0];
    const int* ei = (const int*)d_in[1];
    const float* Wl[3] = {(const float*)d_in[2], (const float*)d_in[7], (const float*)d_in[12]};
    const float* bl[3] = {(const float*)d_in[3], (const float*)d_in[8], (const float*)d_in[13]};
    const float* Wr[3] = {(const float*)d_in[4], (const float*)d_in[9], (const float*)d_in[14]};
    const float* gm[3] = {(const float*)d_in[5], (const float*)d_in[10], (const float*)d_in[15]};
    const float* bt[3] = {(const float*)d_in[6], (const float*)d_in[11], (const float*)d_in[16]};
    int E = in_sizes[1] / 2;

    void *p_h0, *p_h1, *p_deg, *p_wt;
    cudaGetSymbolAddress(&p_h0, g_h0);
    cudaGetSymbolAddress(&p_h1, g_h1);
    cudaGetSymbolAddress(&p_deg, g_deg);
    cudaGetSymbolAddress(&p_wt, g_Wt3);
    __half* h0 = (__half*)p_h0;
    __half* h1 = (__half*)p_h1;
    const float* Wt = (const float*)p_wt;

    // ---- weight prep for all 3 layers (one launch) ----
    prep_w_all<<<(3 * K2 * DD + 255) / 256, 256>>>(Wl[0], Wr[0], Wl[1], Wr[1], Wl[2], Wr[2]);

    // ---- build CSR once per call ----
    const int NB = (NN + 1023) / 1024;  // 49
    zero_i4<<<(12500 + 255) / 256, 256>>>((int*)p_deg, 12500);
    count_kernel<<<(E + 255) / 256, 256>>>(ei, E);
    scan1_kernel<<<NB, 1024>>>();
    scan2_kernel<<<1, 64>>>(NB);
    scan3_kernel<<<NB, 1024>>>();
    fill_kernel<<<(E + 255) / 256, 256>>>(ei, E);

    const int GB = (NN * 32 + 255) / 256;
    const int MB = (NN + 127) / 128;

    // ---- layer 0: x (fp32) -> h0 (fp16) ----
    gather_f32<<<GB, 256>>>(x);
    gemm_kernel<float, 0, __half><<<MB, 128>>>(x, Wt, bl[0], h0);
    finalize_kernel<<<1, 128>>>(gm[0], bt[0]);

    // ---- layer 1: h0 (fp16) -> h1 (fp16) ----
    gather_f16<<<GB, 256>>>(h0);
    gemm_kernel<__half, 1, __half><<<MB, 128>>>(h0, Wt + K2 * DD, bl[1], h1);
    finalize_kernel<<<1, 128>>>(gm[1], bt[1]);

    // ---- layer 2: h1 (fp16) -> d_out (fp32) ----
    gather_f16<<<GB, 256>>>(h1);
    gemm_kernel<__half, 1, float><<<MB, 128>>>(h1, Wt + 2 * K2 * DD, bl[2], (float*)d_out);
    finalize_kernel<<<1, 128>>>(gm[2], bt[2]);
    apply_kernel<<<(NN * DD / 4 + 255) / 256, 256>>>((float*)d_out);
}

// round 7
// speedup vs baseline: 1.9676x; 1.0210x over previous
#include <cuda_runtime.h>
#include <cuda_fp16.h>
#include <cstdint>
#include <type_traits>

#define NN 50000
#define DD 128
#define K2 256
#define EE 800000
#define EPS 1e-5f

// ---------------- scratch (device globals) ----------------------------------
__device__ float  g_agg[NN * DD];      // mean-aggregated (transformed) features, fp32
__device__ __half g_h0[NN * DD];       // layer 0 pre-BN output (fp16)
__device__ __half g_h1[NN * DD];       // layer 1 pre-BN output (fp16)
__device__ float  g_Wt3[3 * K2 * DD];  // combined transposed weights per layer
__device__ float  g_stats[4 * DD];     // [sum | sumsq | scale | shift]
__device__ int    g_deg[NN];
__device__ int    g_rowptr[NN + 1];
__device__ int    g_cursor[NN];
__device__ int    g_col[EE];
__device__ int    g_bsum[64];
__device__ int    g_scan_count;

// ---------------- CSR build --------------------------------------------------
__global__ void count_kernel(const int* __restrict__ ei, int E) {
    int e = blockIdx.x * blockDim.x + threadIdx.x;
    if (e < E) {
        int d = ei[E + e];
        if (d >= 0 && d < NN) atomicAdd(&g_deg[d], 1);
    }
}

// single-kernel scan: all 49 blocks co-resident (1024 thr -> 2 blocks/SM, 148 SMs)
__global__ void scan_fused_kernel() {
    __shared__ int wsum[32];
    __shared__ int s_off;
    int t = threadIdx.x, b = blockIdx.x;
    int idx = b * 1024 + t;
    int wid = t >> 5, lane = t & 31;
    int v = (idx < NN) ? g_deg[idx] : 0;
    int incl = v;
#pragma unroll
    for (int off = 1; off < 32; off <<= 1) {
        int y = __shfl_up_sync(0xffffffffu, incl, off);
        if (lane >= off) incl += y;
    }
    if (lane == 31) wsum[wid] = incl;
    __syncthreads();
    if (wid == 0) {
        int si = wsum[lane];
#pragma unroll
        for (int off = 1; off < 32; off <<= 1) {
            int y = __shfl_up_sync(0xffffffffu, si, off);
            if (lane >= off) si += y;
        }
        wsum[lane] = si;
    }
    __syncthreads();
    int total = wsum[31];
    if (t == 0) {
        g_bsum[b] = total;
        __threadfence();
        atomicAdd(&g_scan_count, 1);
        while (atomicAdd(&g_scan_count, 0) < (int)gridDim.x) {}
        __threadfence();
        int off = 0;
        for (int j = 0; j < b; j++) off += g_bsum[j];
        s_off = off;
    }
    __syncthreads();
    int woff = (wid > 0) ? wsum[wid - 1] : 0;
    if (idx < NN) {
        int r = s_off + woff + incl - v;
        g_rowptr[idx] = r;
        g_cursor[idx] = r;
    }
    if (b == gridDim.x - 1 && t == 0) g_rowptr[NN] = s_off + total;
}

__global__ void fill_kernel(const int* __restrict__ ei, int E) {
    int e = blockIdx.x * blockDim.x + threadIdx.x;
    if (e < E) {
        int s = ei[e];
        int d = ei[E + e];
        if (d >= 0 && d < NN) {
            int pos = atomicAdd(&g_cursor[d], 1);
            g_col[pos] = s;
        }
    }
}

// ---------------- gather (fp32 input, layer 0): also zeroes BN accumulators --
__global__ void gather_f32(const float* __restrict__ x) {
    if (blockIdx.x == 0 && threadIdx.x < 2 * DD) g_stats[threadIdx.x] = 0.f;
    int w = (blockIdx.x * blockDim.x + threadIdx.x) >> 5;
    int lane = threadIdx.x & 31;
    if (w >= NN) return;
    int start = g_rowptr[w], end = g_rowptr[w + 1];
    float4 acc = make_float4(0.f, 0.f, 0.f, 0.f);
    int i = start;
    for (; i + 7 < end; i += 8) {
        int sidx[8];
#pragma unroll
        for (int u = 0; u < 8; u++) sidx[u] = __ldg(&g_col[i + u]);
        float4 vv[8];
#pragma unroll
        for (int u = 0; u < 8; u++)
            vv[u] = __ldg((const float4*)(x + (size_t)sidx[u] * DD) + lane);
#pragma unroll
        for (int u = 0; u < 8; u++) {
            acc.x += vv[u].x; acc.y += vv[u].y;
            acc.z += vv[u].z; acc.w += vv[u].w;
        }
    }
    for (; i < end; i++) {
        int s = __ldg(&g_col[i]);
        float4 v = __ldg((const float4*)(x + (size_t)s * DD) + lane);
        acc.x += v.x; acc.y += v.y; acc.z += v.z; acc.w += v.w;
    }
    float sc = 1.0f / fmaxf((float)(end - start), 1.0f);
    acc.x *= sc; acc.y *= sc; acc.z *= sc; acc.w *= sc;
    ((float4*)(g_agg + (size_t)w * DD))[lane] = acc;
}

// ---------------- gather (fp16 input + fused BN+ReLU), layers 1/2 -----------
__global__ void gather_f16(const __half* __restrict__ x) {
    if (blockIdx.x == 0 && threadIdx.x < 2 * DD) g_stats[threadIdx.x] = 0.f;
    int w = (blockIdx.x * blockDim.x + threadIdx.x) >> 5;
    int lane = threadIdx.x & 31;
    if (w >= NN) return;
    float4 s4 = ((const float4*)(g_stats + 2 * DD))[lane];
    float4 b4 = ((const float4*)(g_stats + 3 * DD))[lane];
    int start = g_rowptr[w], end = g_rowptr[w + 1];
    float4 acc = make_float4(0.f, 0.f, 0.f, 0.f);

    auto addv = [&](uint2 raw) {
        __half2 h0 = *reinterpret_cast<__half2*>(&raw.x);
        __half2 h1 = *reinterpret_cast<__half2*>(&raw.y);
        float2 f0 = __half22float2(h0);
        float2 f1 = __half22float2(h1);
        acc.x += fmaxf(fmaf(f0.x, s4.x, b4.x), 0.f);
        acc.y += fmaxf(fmaf(f0.y, s4.y, b4.y), 0.f);
        acc.z += fmaxf(fmaf(f1.x, s4.z, b4.z), 0.f);
        acc.w += fmaxf(fmaf(f1.y, s4.w, b4.w), 0.f);
    };

    int i = start;
    for (; i + 7 < end; i += 8) {
        int sidx[8];
#pragma unroll
        for (int u = 0; u < 8; u++) sidx[u] = __ldg(&g_col[i + u]);
        uint2 rr[8];
#pragma unroll
        for (int u = 0; u < 8; u++)
            rr[u] = __ldg((const uint2*)(x + (size_t)sidx[u] * DD) + lane);
#pragma unroll
        for (int u = 0; u < 8; u++) addv(rr[u]);
    }
    for (; i < end; i++) {
        int s = __ldg(&g_col[i]);
        addv(__ldg((const uint2*)(x + (size_t)s * DD) + lane));
    }
    float sc = 1.0f / fmaxf((float)(end - start), 1.0f);
    acc.x *= sc; acc.y *= sc; acc.z *= sc; acc.w *= sc;
    ((float4*)(g_agg + (size_t)w * DD))[lane] = acc;
}

// ---------------- weight prep (all layers) + deg zero + scan reset ----------
__global__ void prep_w_all(const float* __restrict__ Wl0, const float* __restrict__ Wr0,
                           const float* __restrict__ Wl1, const float* __restrict__ Wr1,
                           const float* __restrict__ Wl2, const float* __restrict__ Wr2) {
    int i = blockIdx.x * blockDim.x + threadIdx.x;
    if (i == 0) g_scan_count = 0;
    if (i < NN / 4) ((int4*)g_deg)[i] = make_int4(0, 0, 0, 0);
    if (i >= 3 * K2 * DD) return;
    int L = i / (K2 * DD);
    int r = i - L * (K2 * DD);
    int k = r >> 7, j = r & 127;
    const float* Wl = (L == 0) ? Wl0 : (L == 1 ? Wl1 : Wl2);
    const float* Wr = (L == 0) ? Wr0 : (L == 1 ? Wr1 : Wr2);
    g_Wt3[i] = (k < DD) ? __ldg(&Wl[j * DD + k]) : __ldg(&Wr[j * DD + (k - DD)]);
}

// ---------------- 3xTF32 tensor-core GEMM + fused BN stats ------------------
#define ASTRIDE 20
#define BSTRIDE 136

__device__ __forceinline__ void split_tf32(float v, uint32_t& hi, uint32_t& lo) {
    asm("cvt.rna.tf32.f32 %0, %1;" : "=r"(hi) : "f"(v));
    float l = v - __uint_as_float(hi);
    asm("cvt.rna.tf32.f32 %0, %1;" : "=r"(lo) : "f"(l));
}

__device__ __forceinline__ void mma_tf32(float* d, uint32_t a0, uint32_t a1,
                                         uint32_t a2, uint32_t a3,
                                         uint32_t b0, uint32_t b1) {
    asm volatile(
        "mma.sync.aligned.m16n8k8.row.col.f32.tf32.tf32.f32 "
        "{%0,%1,%2,%3},{%4,%5,%6,%7},{%8,%9},{%0,%1,%2,%3};"
        : "+f"(d[0]), "+f"(d[1]), "+f"(d[2]), "+f"(d[3])
        : "r"(a0), "r"(a1), "r"(a2), "r"(a3), "r"(b0), "r"(b1));
}

template <typename TI, int XFORM, typename TO>
__global__ __launch_bounds__(128, 2)
void gemm_kernel(const TI* __restrict__ Xin,
                 const float* __restrict__ Wt,
                 const float* __restrict__ bias,
                 TO* __restrict__ Y) {
    __shared__ float As_hi[128 * ASTRIDE];
    __shared__ float As_lo[128 * ASTRIDE];
    __shared__ float Bs_hi[16 * BSTRIDE];
    __shared__ float Bs_lo[16 * BSTRIDE];
    __shared__ float bias_s[128];

    int tid = threadIdx.x;
    int brow = blockIdx.x * 128;
    int wid = tid >> 5, lane = tid & 31;
    int group = lane >> 2, tg = lane & 3;
    int warp_m = (wid >> 1) * 64, warp_n = (wid & 1) * 64;

    if (tid < 128) bias_s[tid] = __ldg(&bias[tid]);

    float acc[4][8][4];
#pragma unroll
    for (int mt = 0; mt < 4; mt++)
#pragma unroll
        for (int nt = 0; nt < 8; nt++)
#pragma unroll
            for (int c = 0; c < 4; c++) acc[mt][nt][c] = 0.f;

    float4 pa[4], pb[4];

    auto load_tiles = [&](int kc) {
#pragma unroll
        for (int i = 0; i < 4; i++) {
            int l = tid + i * 128;
            int row = l >> 2, kq = l & 3;
            int r = brow + row;
            float4 v = make_float4(0.f, 0.f, 0.f, 0.f);
            if (r < NN) {
                if (kc < DD) {
                    v = __ldg((const float4*)(g_agg + (size_t)r * DD + kc) + kq);
                } else {
                    int kg = (kc - DD) + kq * 4;
                    if constexpr (std::is_same_v<TI, __half>) {
                        uint2 raw = __ldg((const uint2*)(Xin + (size_t)r * DD + kg));
                        __half2 h0 = *reinterpret_cast<__half2*>(&raw.x);
                        __half2 h1 = *reinterpret_cast<__half2*>(&raw.y);
                        float2 f0 = __half22float2(h0);
                        float2 f1 = __half22float2(h1);
                        v = make_float4(f0.x, f0.y, f1.x, f1.y);
                    } else {
                        v = __ldg((const float4*)(Xin + (size_t)r * DD + kg));
                    }
                    if (XFORM) {
                        float4 s4 = *(const float4*)(g_stats + 2 * DD + kg);
                        float4 b4 = *(const float4*)(g_stats + 3 * DD + kg);
                        v.x = fmaxf(fmaf(v.x, s4.x, b4.x), 0.f);
                        v.y = fmaxf(fmaf(v.y, s4.y, b4.y), 0.f);
                        v.z = fmaxf(fmaf(v.z, s4.z, b4.z), 0.f);
                        v.w = fmaxf(fmaf(v.w, s4.w, b4.w), 0.f);
                    }
                }
            }
            pa[i] = v;
        }
#pragma unroll
        for (int i = 0; i < 4; i++) {
            int l = tid + i * 128;
            int k = l >> 5, j4 = l & 31;
            pb[i] = __ldg((const float4*)(Wt + (size_t)(kc + k) * DD) + j4);
        }
    };

    auto store_tiles = [&]() {
#pragma unroll
        for (int i = 0; i < 4; i++) {
            int l = tid + i * 128;
            int row = l >> 2, kq = l & 3;
            float vv[4] = {pa[i].x, pa[i].y, pa[i].z, pa[i].w};
#pragma unroll
            for (int c = 0; c < 4; c++) {
                uint32_t h, lo;
                split_tf32(vv[c], h, lo);
                As_hi[row * ASTRIDE + kq * 4 + c] = __uint_as_float(h);
                As_lo[row * ASTRIDE + kq * 4 + c] = __uint_as_float(lo);
            }
        }
#pragma unroll
        for (int i = 0; i < 4; i++) {
            int l = tid + i * 128;
            int k = l >> 5, j4 = l & 31;
            float vv[4] = {pb[i].x, pb[i].y, pb[i].z, pb[i].w};
#pragma unroll
            for (int c = 0; c < 4; c++) {
                uint32_t h, lo;
                split_tf32(vv[c], h, lo);
                Bs_hi[k * BSTRIDE + j4 * 4 + c] = __uint_as_float(h);
                Bs_lo[k * BSTRIDE + j4 * 4 + c] = __uint_as_float(lo);
            }
        }
    };

    load_tiles(0);

    for (int kc = 0; kc < K2; kc += 16) {
        store_tiles();
        __syncthreads();
        if (kc + 16 < K2) load_tiles(kc + 16);

#pragma unroll
        for (int k0 = 0; k0 < 16; k0 += 8) {
            uint32_t bh0[8], bh1[8], bl0[8], bl1[8];
#pragma unroll
            for (int nt = 0; nt < 8; nt++) {
                int n = warp_n + nt * 8 + group;
                bh0[nt] = __float_as_uint(Bs_hi[(k0 + tg) * BSTRIDE + n]);
                bh1[nt] = __float_as_uint(Bs_hi[(k0 + tg + 4) * BSTRIDE + n]);
                bl0[nt] = __float_as_uint(Bs_lo[(k0 + tg) * BSTRIDE + n]);
                bl1[nt] = __float_as_uint(Bs_lo[(k0 + tg + 4) * BSTRIDE + n]);
            }
#pragma unroll
            for (int mt = 0; mt < 4; mt++) {
                int m = warp_m + mt * 16;
                uint32_t ah0 = __float_as_uint(As_hi[(m + group) * ASTRIDE + k0 + tg]);
                uint32_t ah1 = __float_as_uint(As_hi[(m + group + 8) * ASTRIDE + k0 + tg]);
                uint32_t ah2 = __float_as_uint(As_hi[(m + group) * ASTRIDE + k0 + tg + 4]);
                uint32_t ah3 = __float_as_uint(As_hi[(m + group + 8) * ASTRIDE + k0 + tg + 4]);
                uint32_t al0 = __float_as_uint(As_lo[(m + group) * ASTRIDE + k0 + tg]);
                uint32_t al1 = __float_as_uint(As_lo[(m + group + 8) * ASTRIDE + k0 + tg]);
                uint32_t al2 = __float_as_uint(As_lo[(m + group) * ASTRIDE + k0 + tg + 4]);
                uint32_t al3 = __float_as_uint(As_lo[(m + group + 8) * ASTRIDE + k0 + tg + 4]);
#pragma unroll
                for (int nt = 0; nt < 8; nt++) {
                    mma_tf32(acc[mt][nt], ah0, ah1, ah2, ah3, bh0[nt], bh1[nt]);
                    mma_tf32(acc[mt][nt], al0, al1, al2, al3, bh0[nt], bh1[nt]);
                    mma_tf32(acc[mt][nt], ah0, ah1, ah2, ah3, bl0[nt], bl1[nt]);
                }
            }
        }
        __syncthreads();
    }

    float cs[16], cq[16];
#pragma unroll
    for (int i = 0; i < 16; i++) { cs[i] = 0.f; cq[i] = 0.f; }

#pragma unroll
    for (int mt = 0; mt < 4; mt++) {
        int r0 = brow + warp_m + mt * 16 + group;
        int r1 = r0 + 8;
#pragma unroll
        for (int nt = 0; nt < 8; nt++) {
            int c = warp_n + nt * 8 + 2 * tg;
            float b0 = bias_s[c], b1 = bias_s[c + 1];
            float o0 = acc[mt][nt][0] + b0, o1 = acc[mt][nt][1] + b1;
            float o2 = acc[mt][nt][2] + b0, o3 = acc[mt][nt][3] + b1;
            if (r0 < NN) {
                if constexpr (std::is_same_v<TO, __half>) {
                    *(__half2*)(Y + (size_t)r0 * DD + c) = __floats2half2_rn(o0, o1);
                } else {
                    *(float2*)(Y + (size_t)r0 * DD + c) = make_float2(o0, o1);
                }
                cs[nt * 2 + 0] += o0; cq[nt * 2 + 0] += o0 * o0;
                cs[nt * 2 + 1] += o1; cq[nt * 2 + 1] += o1 * o1;
            }
            if (r1 < NN) {
                if constexpr (std::is_same_v<TO, __half>) {
                    *(__half2*)(Y + (size_t)r1 * DD + c) = __floats2half2_rn(o2, o3);
                } else {
                    *(float2*)(Y + (size_t)r1 * DD + c) = make_float2(o2, o3);
                }
                cs[nt * 2 + 0] += o2; cq[nt * 2 + 0] += o2 * o2;
                cs[nt * 2 + 1] += o3; cq[nt * 2 + 1] += o3 * o3;
            }
        }
    }
#pragma unroll
    for (int i = 0; i < 16; i++) {
#pragma unroll
        for (int off = 4; off < 32; off <<= 1) {
            cs[i] += __shfl_xor_sync(0xffffffffu, cs[i], off);
            cq[i] += __shfl_xor_sync(0xffffffffu, cq[i], off);
        }
    }
    if (group == 0) {
#pragma unroll
        for (int i = 0; i < 16; i++) {
            int c = warp_n + (i >> 1) * 8 + 2 * tg + (i & 1);
            atomicAdd(&g_stats[c], cs[i]);
            atomicAdd(&g_stats[DD + c], cq[i]);
        }
    }
}

// ---------------- BN finalize + final apply ----------------------------------
__global__ void finalize_kernel(const float* __restrict__ gamma,
                                const float* __restrict__ beta) {
    int c = threadIdx.x;
    float m = g_stats[c] * (1.0f / NN);
    float var = g_stats[DD + c] * (1.0f / NN) - m * m;
    float sc = __ldg(&gamma[c]) * rsqrtf(var + EPS);
    g_stats[2 * DD + c] = sc;
    g_stats[3 * DD + c] = __ldg(&beta[c]) - m * sc;
}

__global__ void apply_kernel(float* __restrict__ Y) {
    int i = blockIdx.x * blockDim.x + threadIdx.x;
    if (i >= NN * (DD / 4)) return;
    float4 v = ((float4*)Y)[i];
    int c = (i & (DD / 4 - 1)) * 4;
    float s0 = g_stats[2 * DD + c + 0], b0 = g_stats[3 * DD + c + 0];
    float s1 = g_stats[2 * DD + c + 1], b1 = g_stats[3 * DD + c + 1];
    float s2 = g_stats[2 * DD + c + 2], b2 = g_stats[3 * DD + c + 2];
    float s3 = g_stats[2 * DD + c + 3], b3 = g_stats[3 * DD + c + 3];
    v.x = v.x * s0 + b0;
    v.y = v.y * s1 + b1;
    v.z = v.z * s2 + b2;
    v.w = v.w * s3 + b3;
    ((float4*)Y)[i] = v;
}

// ---------------- launch ----------------------------------------------------
extern "C" void kernel_launch(void* const* d_in, const int* in_sizes, int n_in,
                              void* d_out, int out_size) {
    const float* x = (const float*)d_in[0];
    const int* ei = (const int*)d_in[1];
    const float* Wl[3] = {(const float*)d_in[2], (const float*)d_in[7], (const float*)d_in[12]};
    const float* bl[3] = {(const float*)d_in[3], (const float*)d_in[8], (const float*)d_in[13]};
    const float* Wr[3] = {(const float*)d_in[4], (const float*)d_in[9], (const float*)d_in[14]};
    const float* gm[3] = {(const float*)d_in[5], (const float*)d_in[10], (const float*)d_in[15]};
    const float* bt[3] = {(const float*)d_in[6], (const float*)d_in[11], (const float*)d_in[16]};
    int E = in_sizes[1] / 2;

    void *p_h0, *p_h1, *p_wt;
    cudaGetSymbolAddress(&p_h0, g_h0);
    cudaGetSymbolAddress(&p_h1, g_h1);
    cudaGetSymbolAddress(&p_wt, g_Wt3);
    __half* h0 = (__half*)p_h0;
    __half* h1 = (__half*)p_h1;
    const float* Wt = (const float*)p_wt;

    // weight prep + deg zero + scan-counter reset (one launch)
    prep_w_all<<<(3 * K2 * DD + 255) / 256, 256>>>(Wl[0], Wr[0], Wl[1], Wr[1], Wl[2], Wr[2]);

    // CSR build
    const int NB = (NN + 1023) / 1024;  // 49 blocks, all co-resident
    count_kernel<<<(E + 255) / 256, 256>>>(ei, E);
    scan_fused_kernel<<<NB, 1024>>>();
    fill_kernel<<<(E + 255) / 256, 256>>>(ei, E);

    const int GB = (NN * 32 + 255) / 256;
    const int MB = (NN + 127) / 128;

    // layer 0: x (fp32) -> h0 (fp16)
    gather_f32<<<GB, 256>>>(x);
    gemm_kernel<float, 0, __half><<<MB, 128>>>(x, Wt, bl[0], h0);
    finalize_kernel<<<1, 128>>>(gm[0], bt[0]);

    // layer 1: h0 (fp16) -> h1 (fp16)
    gather_f16<<<GB, 256>>>(h0);
    gemm_kernel<__half, 1, __half><<<MB, 128>>>(h0, Wt + K2 * DD, bl[1], h1);
    finalize_kernel<<<1, 128>>>(gm[1], bt[1]);

    // layer 2: h1 (fp16) -> d_out (fp32)
    gather_f16<<<GB, 256>>>(h1);
    gemm_kernel<__half, 1, float><<<MB, 128>>>(h1, Wt + 2 * K2 * DD, bl[2], (float*)d_out);
    finalize_kernel<<<1, 128>>>(gm[2], bt[2]);
    apply_kernel<<<(NN * DD / 4 + 255) / 256, 256>>>((float*)d_out);
}